// round 7
// baseline (speedup 1.0000x reference)
#include <cuda_runtime.h>
#include <cuda_bf16.h>
#include <cstdint>
#include <cstddef>

// Problem constants
#define C_ 4
#define B_ 64
#define T_ 512
#define D_ 256
#define U_ 512
#define OSC_ 5

// ---------------------------------------------------------------------------
// Scratch (device globals — no allocation allowed)
// ---------------------------------------------------------------------------
// xproj[(c*2+g)][t][b][u] : input projections incl. bjx/bkx. 8*512*64*512 floats
__device__ float g_xproj[8ull * T_ * B_ * U_];
// seq[c][t][b][u] : scan outputs (h_t). 4*512*64*512 floats
__device__ float g_seq[(size_t)C_ * T_ * B_ * U_];

// grid barrier state (count returns to 0 after each barrier; gen monotonic)
__device__ unsigned g_bar_count = 0;
__device__ unsigned g_bar_gen = 0;

// ---------------------------------------------------------------------------
// Phase 1: input projection GEMM
//   xproj[(c*2+g)][t][b][u] = sum_d x[b][t][d] * W[c][d][u] + bias[c][u]
//   GEMM: M = B*T (m = b*T + t, matching x row layout), N = U, K = D.
// ---------------------------------------------------------------------------
#define PBM 128
#define PBN 64
#define PBK 8

__global__ __launch_bounds__(256) void proj_kernel(
    const float* __restrict__ x,
    const float* __restrict__ Wjx, const float* __restrict__ bjx,
    const float* __restrict__ Wkx, const float* __restrict__ bkx)
{
    __shared__ float As[PBK][PBM];
    __shared__ float Bs[PBK][PBN];

    const int zi = blockIdx.z;          // 0..7 = c*2+g
    const int c  = zi >> 1;
    const int g  = zi & 1;
    const float* W  = (g ? Wkx : Wjx) + (size_t)c * D_ * U_;
    const float* bi = (g ? bkx : bjx) + (size_t)c * U_;

    const int m0 = blockIdx.x * PBM;
    const int n0 = blockIdx.y * PBN;
    const int tid = threadIdx.x;
    const int tx = tid & 15;            // 0..15 -> 4 cols each
    const int ty = tid >> 4;            // 0..15 -> 8 rows each

    float acc[8][4];
#pragma unroll
    for (int i = 0; i < 8; i++)
#pragma unroll
        for (int j = 0; j < 4; j++) acc[i][j] = 0.f;

    const int arow = tid >> 1;          // 0..127
    const int ak   = (tid & 1) << 2;    // 0 or 4
    const int brow = tid >> 4;          // 0..15 (valid for tid<128 -> 0..7)
    const int bcol = (tid & 15) << 2;

    for (int k0 = 0; k0 < D_; k0 += PBK) {
        float4 av = *(const float4*)&x[(size_t)(m0 + arow) * D_ + k0 + ak];
        float4 bv = make_float4(0.f, 0.f, 0.f, 0.f);
        if (tid < 128)
            bv = *(const float4*)&W[(size_t)(k0 + brow) * U_ + n0 + bcol];
        __syncthreads();
        As[ak + 0][arow] = av.x;
        As[ak + 1][arow] = av.y;
        As[ak + 2][arow] = av.z;
        As[ak + 3][arow] = av.w;
        if (tid < 128)
            *(float4*)&Bs[brow][bcol] = bv;
        __syncthreads();
#pragma unroll
        for (int kk = 0; kk < PBK; kk++) {
            float4 b4 = *(float4*)&Bs[kk][tx << 2];
            float4 a0 = *(float4*)&As[kk][ty << 3];
            float4 a1 = *(float4*)&As[kk][(ty << 3) + 4];
            float av8[8] = {a0.x, a0.y, a0.z, a0.w, a1.x, a1.y, a1.z, a1.w};
            float bv4[4] = {b4.x, b4.y, b4.z, b4.w};
#pragma unroll
            for (int i = 0; i < 8; i++)
#pragma unroll
                for (int j = 0; j < 4; j++)
                    acc[i][j] = fmaf(av8[i], bv4[j], acc[i][j]);
        }
    }

    float4 bias4 = *(const float4*)&bi[n0 + (tx << 2)];
#pragma unroll
    for (int i = 0; i < 8; i++) {
        int m  = m0 + (ty << 3) + i;
        int bb = m >> 9;                // m / T_
        int tt = m & 511;               // m % T_
        float4 o;
        o.x = acc[i][0] + bias4.x;
        o.y = acc[i][1] + bias4.y;
        o.z = acc[i][2] + bias4.z;
        o.w = acc[i][3] + bias4.w;
        size_t off = ((size_t)((zi * T_) + tt) * B_ + bb) * U_ + n0 + (tx << 2);
        *(float4*)&g_xproj[off] = o;
    }
}

// ---------------------------------------------------------------------------
// Phase 2: persistent flip-flop scan with grid barrier per timestep.
//   Block = (cell c, u-chunk of 16). Weights live in registers:
//     warp w (8) owns k-range [w*64, w*64+64); lane l owns (u = l&15, g = l>>4).
//   Per step: stage h[c] (64x512) into smem, each lane FMAs its 64-k slice of
//   W against broadcast h, partials reduced via smem, gates + flip-flop update,
//   write h_t to g_seq, grid barrier.
// ---------------------------------------------------------------------------
#define SC_UC   16                       // u per block
#define SC_NCH  (U_ / SC_UC)             // 32 chunks
#define SC_NBLK (C_ * SC_NCH)            // 128 blocks
#define SC_NTH  256
#define SC_NW   8
#define SC_KW   (U_ / SC_NW)             // 64 k per warp
#define SC_SMEM_FLOATS (B_ * U_ + SC_NW * B_ * 32 + 32)
#define SC_SMEM_BYTES  (SC_SMEM_FLOATS * 4)

__device__ __forceinline__ void grid_barrier_all(unsigned nblocks)
{
    __threadfence();          // publish this thread's global writes
    __syncthreads();          // all threads of block fenced + arrived
    if (threadIdx.x == 0) {
        unsigned gen0 = *(volatile unsigned*)&g_bar_gen;
        unsigned arr  = atomicAdd(&g_bar_count, 1u);
        if (arr == nblocks - 1) {
            g_bar_count = 0;
            __threadfence();
            atomicAdd(&g_bar_gen, 1u);
        } else {
            while (*(volatile unsigned*)&g_bar_gen == gen0) {
                __nanosleep(32);
            }
        }
        __threadfence();
    }
    __syncthreads();
}

__global__ __launch_bounds__(SC_NTH, 1) void scan_kernel(
    const float* __restrict__ h0,
    const float* __restrict__ Wjh, const float* __restrict__ bjh,
    const float* __restrict__ Wkh, const float* __restrict__ bkh)
{
    extern __shared__ float sm[];
    float* h_s    = sm;                        // [B_][U_]          32768 floats
    float* part   = sm + B_ * U_;              // [NW][B_][32]      16384 floats
    float* bias_s = part + SC_NW * B_ * 32;    // [2][16]              32 floats

    const int blk = blockIdx.x;
    const int c   = blk / SC_NCH;
    const int ch  = blk % SC_NCH;
    const int u0  = ch * SC_UC;
    const int tid = threadIdx.x;
    const int w   = tid >> 5;
    const int l   = tid & 31;
    const int lu  = l & 15;                    // lane's u offset
    const int lg  = l >> 4;                    // lane's gate (0=j, 1=k)

    // Load this lane's weight column slice into registers (one-time).
    const float* Wsrc = (lg ? Wkh : Wjh) + (size_t)c * U_ * U_;
    float wreg[SC_KW];
#pragma unroll
    for (int i = 0; i < SC_KW; i++)
        wreg[i] = Wsrc[(size_t)(w * SC_KW + i) * U_ + u0 + lu];

    if (tid < 32)
        bias_s[tid] = ((tid >> 4) ? bkh : bjh)[c * U_ + u0 + (tid & 15)];

    for (int t = 0; t < T_; t++) {
        // ---- stage h (previous output, or h0) into smem, coalesced ----
        const float4* hsrc = (const float4*)((t == 0)
            ? (h0 + (size_t)c * B_ * U_)
            : (g_seq + ((size_t)(c * T_ + (t - 1)) * B_ * U_)));
        float4* hdst = (float4*)h_s;
#pragma unroll
        for (int ii = 0; ii < (B_ * U_ / 4) / SC_NTH; ii++)
            hdst[tid + ii * SC_NTH] = __ldcg(&hsrc[tid + ii * SC_NTH]);
        __syncthreads();

        // ---- partial matvecs: 4 batch rows at a time for ILP ----
        for (int b = 0; b < B_; b += 4) {
            const float4* h0p = (const float4*)&h_s[(b + 0) * U_ + w * SC_KW];
            const float4* h1p = (const float4*)&h_s[(b + 1) * U_ + w * SC_KW];
            const float4* h2p = (const float4*)&h_s[(b + 2) * U_ + w * SC_KW];
            const float4* h3p = (const float4*)&h_s[(b + 3) * U_ + w * SC_KW];
            float a0 = 0.f, a1 = 0.f, a2 = 0.f, a3 = 0.f;
#pragma unroll
            for (int i = 0; i < SC_KW / 4; i++) {
                float4 v0 = h0p[i];
                float4 v1 = h1p[i];
                float4 v2 = h2p[i];
                float4 v3 = h3p[i];
                a0 = fmaf(v0.x, wreg[4*i+0], a0);
                a1 = fmaf(v1.x, wreg[4*i+0], a1);
                a2 = fmaf(v2.x, wreg[4*i+0], a2);
                a3 = fmaf(v3.x, wreg[4*i+0], a3);
                a0 = fmaf(v0.y, wreg[4*i+1], a0);
                a1 = fmaf(v1.y, wreg[4*i+1], a1);
                a2 = fmaf(v2.y, wreg[4*i+1], a2);
                a3 = fmaf(v3.y, wreg[4*i+1], a3);
                a0 = fmaf(v0.z, wreg[4*i+2], a0);
                a1 = fmaf(v1.z, wreg[4*i+2], a1);
                a2 = fmaf(v2.z, wreg[4*i+2], a2);
                a3 = fmaf(v3.z, wreg[4*i+2], a3);
                a0 = fmaf(v0.w, wreg[4*i+3], a0);
                a1 = fmaf(v1.w, wreg[4*i+3], a1);
                a2 = fmaf(v2.w, wreg[4*i+3], a2);
                a3 = fmaf(v3.w, wreg[4*i+3], a3);
            }
            part[(w * B_ + b + 0) * 32 + l] = a0;
            part[(w * B_ + b + 1) * 32 + l] = a1;
            part[(w * B_ + b + 2) * 32 + l] = a2;
            part[(w * B_ + b + 3) * 32 + l] = a3;
        }
        __syncthreads();

        // ---- combine: reduce partials, gates, flip-flop update, write ----
        float* seqout = g_seq + ((size_t)(c * T_ + t) * B_ * U_);
        const float* xj = g_xproj + ((size_t)((c * 2 + 0) * T_ + t) * B_ * U_);
        const float* xk = g_xproj + ((size_t)((c * 2 + 1) * T_ + t) * B_ * U_);
#pragma unroll
        for (int r = 0; r < 4; r++) {
            int p  = tid + r * SC_NTH;      // 0..1023 = (b, u) pairs
            int pu = p & 15;
            int pb = p >> 4;
            float sj = 0.f, sk = 0.f;
#pragma unroll
            for (int ww = 0; ww < SC_NW; ww++) {
                sj += part[(ww * B_ + pb) * 32 + pu];
                sk += part[(ww * B_ + pb) * 32 + pu + 16];
            }
            float zj = sj + xj[pb * U_ + u0 + pu] + bias_s[pu];
            float zk = sk + xk[pb * U_ + u0 + pu] + bias_s[16 + pu];
            float jg = __fdividef(1.f, 1.f + __expf(-zj));
            float kg = __fdividef(1.f, 1.f + __expf(-zk));
            float h  = h_s[pb * U_ + u0 + pu];
            float hn = jg * (1.f - h) + (1.f - kg) * h;
            seqout[pb * U_ + u0 + pu] = hn;
        }

        grid_barrier_all(SC_NBLK);
    }
}

// ---------------------------------------------------------------------------
// Phase 3: oscillator unroll.
//   phi/omega/r/mu = seq[0..3][t][b][u]; 5 micro-steps -> out[b][t*5+s][u]
// ---------------------------------------------------------------------------
__global__ __launch_bounds__(256) void osc_kernel(float* __restrict__ out)
{
    int n = blockIdx.x * 256 + threadIdx.x;      // 0 .. B*T*U-1
    int u  = n & (U_ - 1);
    int bt = n >> 9;
    int b  = bt & (B_ - 1);
    int t  = bt >> 6;

    size_t base = (size_t)t * B_ * U_ + (size_t)b * U_ + u;
    const size_t plane = (size_t)T_ * B_ * U_;
    float phi = g_seq[0 * plane + base];
    float om  = g_seq[1 * plane + base];
    float r   = g_seq[2 * plane + base];
    float mu  = g_seq[3 * plane + base];

    float* o = out + ((size_t)b * (T_ * OSC_) + (size_t)t * OSC_) * U_ + u;
    o[0] = r * __cosf(phi);
#pragma unroll
    for (int s = 1; s < OSC_; s++) {
        r   = r + (mu - r * r) * r;
        phi = phi + om;
        o[(size_t)s * U_] = r * __cosf(phi);
    }
}

// ---------------------------------------------------------------------------
// Launch
// ---------------------------------------------------------------------------
extern "C" void kernel_launch(void* const* d_in, const int* in_sizes, int n_in,
                              void* d_out, int out_size)
{
    const float* x   = (const float*)d_in[0];
    const float* h0  = (const float*)d_in[1];
    const float* Wjx = (const float*)d_in[2];
    const float* bjx = (const float*)d_in[3];
    const float* Wjh = (const float*)d_in[4];
    const float* bjh = (const float*)d_in[5];
    const float* Wkx = (const float*)d_in[6];
    const float* bkx = (const float*)d_in[7];
    const float* Wkh = (const float*)d_in[8];
    const float* bkh = (const float*)d_in[9];
    float* out = (float*)d_out;
    (void)in_sizes; (void)n_in; (void)out_size;

    cudaFuncSetAttribute(scan_kernel,
                         cudaFuncAttributeMaxDynamicSharedMemorySize,
                         SC_SMEM_BYTES);

    // Phase 1: projections. grid = (M/128, U/64, 8 planes)
    dim3 pg((B_ * T_) / PBM, U_ / PBN, 8);
    proj_kernel<<<pg, 256>>>(x, Wjx, bjx, Wkx, bkx);

    // Phase 2: persistent scan (128 co-resident blocks, software grid barrier)
    scan_kernel<<<SC_NBLK, SC_NTH, SC_SMEM_BYTES>>>(h0, Wjh, bjh, Wkh, bkh);

    // Phase 3: oscillator. B*T*U points / 256
    osc_kernel<<<(B_ * T_ * U_) / 256, 256>>>(out);
}

// round 8
// speedup vs baseline: 1.0595x; 1.0595x over previous
#include <cuda_runtime.h>
#include <cuda_bf16.h>
#include <cstdint>
#include <cstddef>

// Problem constants
#define C_ 4
#define B_ 64
#define T_ 512
#define D_ 256
#define U_ 512
#define OSC_ 5

typedef unsigned long long u64;

// ---------------------------------------------------------------------------
// Packed f32x2 helpers (FFMA2 — 2x fp32 FMA throughput; ptxas never emits it)
// ---------------------------------------------------------------------------
__device__ __forceinline__ u64 ffma2(u64 a, u64 b, u64 c) {
    u64 d;
    asm("fma.rn.f32x2 %0, %1, %2, %3;" : "=l"(d) : "l"(a), "l"(b), "l"(c));
    return d;
}
__device__ __forceinline__ u64 pack2(float lo, float hi) {
    u64 d;
    asm("mov.b64 %0, {%1, %2};" : "=l"(d) : "f"(lo), "f"(hi));
    return d;
}
__device__ __forceinline__ float2 unpack2(u64 v) {
    float2 f;
    asm("mov.b64 {%0, %1}, %2;" : "=f"(f.x), "=f"(f.y) : "l"(v));
    return f;
}

// ---------------------------------------------------------------------------
// Scratch (device globals — no allocation allowed)
// ---------------------------------------------------------------------------
// xproj[(c*2+g)][t][b][u] : input projections incl. biases. 8*512*64*512 floats
__device__ float g_xproj[8ull * T_ * B_ * U_];
// seq[c][t][b][u] : scan outputs (h_t). 4*512*64*512 floats
__device__ float g_seq[(size_t)C_ * T_ * B_ * U_];

// per-cell grid barrier state (4 independent sync domains of 32 blocks)
__device__ unsigned g_bar_count[C_] = {0, 0, 0, 0};
__device__ unsigned g_bar_gen[C_]   = {0, 0, 0, 0};

// ---------------------------------------------------------------------------
// Phase 1: input projection GEMM
//   xproj[(c*2+g)][t][b][u] = sum_d x[b][t][d] * W[c][d][u] + bias[c][u]
//   GEMM: M = B*T (m = b*T + t, matching x row layout), N = U, K = D.
// ---------------------------------------------------------------------------
#define PBM 128
#define PBN 64
#define PBK 8

__global__ __launch_bounds__(256) void proj_kernel(
    const float* __restrict__ x,
    const float* __restrict__ Wjx, const float* __restrict__ bjx,
    const float* __restrict__ Wkx, const float* __restrict__ bkx)
{
    __shared__ float As[PBK][PBM];   // column-major: rows contiguous -> f32x2 pairs
    __shared__ float Bs[PBK][PBN];

    const int zi = blockIdx.z;          // 0..7 = c*2+g
    const int c  = zi >> 1;
    const int g  = zi & 1;
    const float* W  = (g ? Wkx : Wjx) + (size_t)c * D_ * U_;
    const float* bi = (g ? bkx : bjx) + (size_t)c * U_;

    const int m0 = blockIdx.x * PBM;
    const int n0 = blockIdx.y * PBN;
    const int tid = threadIdx.x;
    const int tx = tid & 15;            // 0..15 -> 4 cols each
    const int ty = tid >> 4;            // 0..15 -> 8 rows each

    // acc2[ip][j]: packed pair of rows (2ip, 2ip+1) x column j
    u64 acc2[4][4];
#pragma unroll
    for (int i = 0; i < 4; i++)
#pragma unroll
        for (int j = 0; j < 4; j++) acc2[i][j] = 0ull;

    const int arow = tid >> 1;          // 0..127
    const int ak   = (tid & 1) << 2;    // 0 or 4
    const int brow = tid >> 4;          // 0..15 (valid for tid<128 -> 0..7)
    const int bcol = (tid & 15) << 2;

    for (int k0 = 0; k0 < D_; k0 += PBK) {
        float4 av = *(const float4*)&x[(size_t)(m0 + arow) * D_ + k0 + ak];
        float4 bv = make_float4(0.f, 0.f, 0.f, 0.f);
        if (tid < 128)
            bv = *(const float4*)&W[(size_t)(k0 + brow) * U_ + n0 + bcol];
        __syncthreads();
        As[ak + 0][arow] = av.x;
        As[ak + 1][arow] = av.y;
        As[ak + 2][arow] = av.z;
        As[ak + 3][arow] = av.w;
        if (tid < 128)
            *(float4*)&Bs[brow][bcol] = bv;
        __syncthreads();
#pragma unroll
        for (int kk = 0; kk < PBK; kk++) {
            // A rows ty*8..ty*8+7 as 4 packed pairs (contiguous in As column)
            ulonglong2 aA = *(const ulonglong2*)&As[kk][ty << 3];
            ulonglong2 aB = *(const ulonglong2*)&As[kk][(ty << 3) + 4];
            float4 b4 = *(float4*)&Bs[kk][tx << 2];
            u64 bb0 = pack2(b4.x, b4.x);
            u64 bb1 = pack2(b4.y, b4.y);
            u64 bb2 = pack2(b4.z, b4.z);
            u64 bb3 = pack2(b4.w, b4.w);

            acc2[0][0] = ffma2(aA.x, bb0, acc2[0][0]);
            acc2[0][1] = ffma2(aA.x, bb1, acc2[0][1]);
            acc2[0][2] = ffma2(aA.x, bb2, acc2[0][2]);
            acc2[0][3] = ffma2(aA.x, bb3, acc2[0][3]);

            acc2[1][0] = ffma2(aA.y, bb0, acc2[1][0]);
            acc2[1][1] = ffma2(aA.y, bb1, acc2[1][1]);
            acc2[1][2] = ffma2(aA.y, bb2, acc2[1][2]);
            acc2[1][3] = ffma2(aA.y, bb3, acc2[1][3]);

            acc2[2][0] = ffma2(aB.x, bb0, acc2[2][0]);
            acc2[2][1] = ffma2(aB.x, bb1, acc2[2][1]);
            acc2[2][2] = ffma2(aB.x, bb2, acc2[2][2]);
            acc2[2][3] = ffma2(aB.x, bb3, acc2[2][3]);

            acc2[3][0] = ffma2(aB.y, bb0, acc2[3][0]);
            acc2[3][1] = ffma2(aB.y, bb1, acc2[3][1]);
            acc2[3][2] = ffma2(aB.y, bb2, acc2[3][2]);
            acc2[3][3] = ffma2(aB.y, bb3, acc2[3][3]);
        }
    }

    // unpack into per-row accumulators
    float accf[8][4];
#pragma unroll
    for (int ip = 0; ip < 4; ip++)
#pragma unroll
        for (int j = 0; j < 4; j++) {
            float2 p = unpack2(acc2[ip][j]);
            accf[2 * ip + 0][j] = p.x;
            accf[2 * ip + 1][j] = p.y;
        }

    float4 bias4 = *(const float4*)&bi[n0 + (tx << 2)];
#pragma unroll
    for (int i = 0; i < 8; i++) {
        int m  = m0 + (ty << 3) + i;
        int bb = m >> 9;                // m / T_
        int tt = m & 511;               // m % T_
        float4 o;
        o.x = accf[i][0] + bias4.x;
        o.y = accf[i][1] + bias4.y;
        o.z = accf[i][2] + bias4.z;
        o.w = accf[i][3] + bias4.w;
        size_t off = ((size_t)((zi * T_) + tt) * B_ + bb) * U_ + n0 + (tx << 2);
        *(float4*)&g_xproj[off] = o;
    }
}

// ---------------------------------------------------------------------------
// Phase 2: persistent flip-flop scan with PER-CELL grid barrier per timestep.
//   Block = (cell c, u-chunk of 16). Weights live in registers as packed
//   f32x2 pairs along k: warp w owns k-range [w*64, w*64+64); lane l owns
//   (u = l&15, gate = l>>4).
// ---------------------------------------------------------------------------
#define SC_UC   16                       // u per block
#define SC_NCH  (U_ / SC_UC)             // 32 chunks (= blocks per cell)
#define SC_NBLK (C_ * SC_NCH)            // 128 blocks
#define SC_NTH  256
#define SC_NW   8
#define SC_KW   (U_ / SC_NW)             // 64 k per warp
#define SC_SMEM_FLOATS (B_ * U_ + SC_NW * B_ * 32 + 32)
#define SC_SMEM_BYTES  (SC_SMEM_FLOATS * 4)

__device__ __forceinline__ void grid_barrier_cell(int c, unsigned nblocks)
{
    __threadfence();          // publish this thread's global writes
    __syncthreads();          // all threads of block fenced + arrived
    if (threadIdx.x == 0) {
        unsigned gen0 = *(volatile unsigned*)&g_bar_gen[c];
        unsigned arr  = atomicAdd(&g_bar_count[c], 1u);
        if (arr == nblocks - 1) {
            g_bar_count[c] = 0;
            __threadfence();
            atomicAdd(&g_bar_gen[c], 1u);
        } else {
            while (*(volatile unsigned*)&g_bar_gen[c] == gen0) {
                __nanosleep(32);
            }
        }
        __threadfence();
    }
    __syncthreads();
}

__global__ __launch_bounds__(SC_NTH, 1) void scan_kernel(
    const float* __restrict__ h0,
    const float* __restrict__ Wjh, const float* __restrict__ bjh,
    const float* __restrict__ Wkh, const float* __restrict__ bkh)
{
    extern __shared__ float sm[];
    float* h_s    = sm;                        // [B_][U_]          32768 floats
    float* part   = sm + B_ * U_;              // [NW][B_][32]      16384 floats
    float* bias_s = part + SC_NW * B_ * 32;    // [2][16]              32 floats

    const int blk = blockIdx.x;
    const int c   = blk / SC_NCH;
    const int ch  = blk % SC_NCH;
    const int u0  = ch * SC_UC;
    const int tid = threadIdx.x;
    const int w   = tid >> 5;
    const int l   = tid & 31;
    const int lu  = l & 15;                    // lane's u offset
    const int lg  = l >> 4;                    // lane's gate (0=j, 1=k)

    // Load this lane's weight column slice, packed into f32x2 pairs along k.
    const float* Wsrc = (lg ? Wkh : Wjh) + (size_t)c * U_ * U_;
    u64 wpair[SC_KW / 2];
#pragma unroll
    for (int i = 0; i < SC_KW / 2; i++) {
        float wlo = Wsrc[(size_t)(w * SC_KW + 2 * i + 0) * U_ + u0 + lu];
        float whi = Wsrc[(size_t)(w * SC_KW + 2 * i + 1) * U_ + u0 + lu];
        wpair[i] = pack2(wlo, whi);
    }

    if (tid < 32)
        bias_s[tid] = ((tid >> 4) ? bkh : bjh)[c * U_ + u0 + (tid & 15)];

    for (int t = 0; t < T_; t++) {
        // ---- stage h (previous output, or h0) into smem, coalesced ----
        const float4* hsrc = (const float4*)((t == 0)
            ? (h0 + (size_t)c * B_ * U_)
            : (g_seq + ((size_t)(c * T_ + (t - 1)) * B_ * U_)));
        float4* hdst = (float4*)h_s;
#pragma unroll
        for (int ii = 0; ii < (B_ * U_ / 4) / SC_NTH; ii++)
            hdst[tid + ii * SC_NTH] = __ldcg(&hsrc[tid + ii * SC_NTH]);
        __syncthreads();

        // ---- partial matvecs via FFMA2: 4 batch rows at a time ----
        for (int b = 0; b < B_; b += 4) {
            const ulonglong2* h0p = (const ulonglong2*)&h_s[(b + 0) * U_ + w * SC_KW];
            const ulonglong2* h1p = (const ulonglong2*)&h_s[(b + 1) * U_ + w * SC_KW];
            const ulonglong2* h2p = (const ulonglong2*)&h_s[(b + 2) * U_ + w * SC_KW];
            const ulonglong2* h3p = (const ulonglong2*)&h_s[(b + 3) * U_ + w * SC_KW];
            u64 a0 = 0ull, a1 = 0ull, a2 = 0ull, a3 = 0ull;
#pragma unroll
            for (int i = 0; i < SC_KW / 4; i++) {
                ulonglong2 v0 = h0p[i];
                ulonglong2 v1 = h1p[i];
                ulonglong2 v2 = h2p[i];
                ulonglong2 v3 = h3p[i];
                a0 = ffma2(v0.x, wpair[2 * i + 0], a0);
                a1 = ffma2(v1.x, wpair[2 * i + 0], a1);
                a2 = ffma2(v2.x, wpair[2 * i + 0], a2);
                a3 = ffma2(v3.x, wpair[2 * i + 0], a3);
                a0 = ffma2(v0.y, wpair[2 * i + 1], a0);
                a1 = ffma2(v1.y, wpair[2 * i + 1], a1);
                a2 = ffma2(v2.y, wpair[2 * i + 1], a2);
                a3 = ffma2(v3.y, wpair[2 * i + 1], a3);
            }
            float2 f0 = unpack2(a0);
            float2 f1 = unpack2(a1);
            float2 f2 = unpack2(a2);
            float2 f3 = unpack2(a3);
            part[(w * B_ + b + 0) * 32 + l] = f0.x + f0.y;
            part[(w * B_ + b + 1) * 32 + l] = f1.x + f1.y;
            part[(w * B_ + b + 2) * 32 + l] = f2.x + f2.y;
            part[(w * B_ + b + 3) * 32 + l] = f3.x + f3.y;
        }
        __syncthreads();

        // ---- combine: reduce partials, gates, flip-flop update, write ----
        float* seqout = g_seq + ((size_t)(c * T_ + t) * B_ * U_);
        const float* xj = g_xproj + ((size_t)((c * 2 + 0) * T_ + t) * B_ * U_);
        const float* xk = g_xproj + ((size_t)((c * 2 + 1) * T_ + t) * B_ * U_);
#pragma unroll
        for (int r = 0; r < 4; r++) {
            int p  = tid + r * SC_NTH;      // 0..1023 = (b, u) pairs
            int pu = p & 15;
            int pb = p >> 4;
            float sj = 0.f, sk = 0.f;
#pragma unroll
            for (int ww = 0; ww < SC_NW; ww++) {
                sj += part[(ww * B_ + pb) * 32 + pu];
                sk += part[(ww * B_ + pb) * 32 + pu + 16];
            }
            float zj = sj + xj[pb * U_ + u0 + pu] + bias_s[pu];
            float zk = sk + xk[pb * U_ + u0 + pu] + bias_s[16 + pu];
            float jg = __fdividef(1.f, 1.f + __expf(-zj));
            float kg = __fdividef(1.f, 1.f + __expf(-zk));
            float h  = h_s[pb * U_ + u0 + pu];
            float hn = jg * (1.f - h) + (1.f - kg) * h;
            seqout[pb * U_ + u0 + pu] = hn;
        }

        grid_barrier_cell(c, SC_NCH);
    }
}

// ---------------------------------------------------------------------------
// Phase 3: oscillator unroll.
//   phi/omega/r/mu = seq[0..3][t][b][u]; 5 micro-steps -> out[b][t*5+s][u]
// ---------------------------------------------------------------------------
__global__ __launch_bounds__(256) void osc_kernel(float* __restrict__ out)
{
    int n = blockIdx.x * 256 + threadIdx.x;      // 0 .. B*T*U-1
    int u  = n & (U_ - 1);
    int bt = n >> 9;
    int b  = bt & (B_ - 1);
    int t  = bt >> 6;

    size_t base = (size_t)t * B_ * U_ + (size_t)b * U_ + u;
    const size_t plane = (size_t)T_ * B_ * U_;
    float phi = g_seq[0 * plane + base];
    float om  = g_seq[1 * plane + base];
    float r   = g_seq[2 * plane + base];
    float mu  = g_seq[3 * plane + base];

    float* o = out + ((size_t)b * (T_ * OSC_) + (size_t)t * OSC_) * U_ + u;
    o[0] = r * __cosf(phi);
#pragma unroll
    for (int s = 1; s < OSC_; s++) {
        r   = r + (mu - r * r) * r;
        phi = phi + om;
        o[(size_t)s * U_] = r * __cosf(phi);
    }
}

// ---------------------------------------------------------------------------
// Launch
// ---------------------------------------------------------------------------
extern "C" void kernel_launch(void* const* d_in, const int* in_sizes, int n_in,
                              void* d_out, int out_size)
{
    const float* x   = (const float*)d_in[0];
    const float* h0  = (const float*)d_in[1];
    const float* Wjx = (const float*)d_in[2];
    const float* bjx = (const float*)d_in[3];
    const float* Wjh = (const float*)d_in[4];
    const float* bjh = (const float*)d_in[5];
    const float* Wkx = (const float*)d_in[6];
    const float* bkx = (const float*)d_in[7];
    const float* Wkh = (const float*)d_in[8];
    const float* bkh = (const float*)d_in[9];
    float* out = (float*)d_out;
    (void)in_sizes; (void)n_in; (void)out_size;

    cudaFuncSetAttribute(scan_kernel,
                         cudaFuncAttributeMaxDynamicSharedMemorySize,
                         SC_SMEM_BYTES);

    // Phase 1: projections. grid = (M/128, U/64, 8 planes)
    dim3 pg((B_ * T_) / PBM, U_ / PBN, 8);
    proj_kernel<<<pg, 256>>>(x, Wjx, bjx, Wkx, bkx);

    // Phase 2: persistent scan (128 co-resident blocks, per-cell grid barrier)
    scan_kernel<<<SC_NBLK, SC_NTH, SC_SMEM_BYTES>>>(h0, Wjh, bjh, Wkh, bkh);

    // Phase 3: oscillator. B*T*U points / 256
    osc_kernel<<<(B_ * T_ * U_) / 256, 256>>>(out);
}

// round 9
// speedup vs baseline: 1.0714x; 1.0112x over previous
#include <cuda_runtime.h>
#include <cuda_bf16.h>
#include <cstdint>
#include <cstddef>

// Problem constants
#define C_ 4
#define B_ 64
#define T_ 512
#define D_ 256
#define U_ 512
#define OSC_ 5

typedef unsigned long long u64;

// ---------------------------------------------------------------------------
// Packed f32x2 helpers (FFMA2 — 2x fp32 FMA throughput; ptxas never emits it)
// ---------------------------------------------------------------------------
__device__ __forceinline__ u64 ffma2(u64 a, u64 b, u64 c) {
    u64 d;
    asm("fma.rn.f32x2 %0, %1, %2, %3;" : "=l"(d) : "l"(a), "l"(b), "l"(c));
    return d;
}
__device__ __forceinline__ u64 pack2(float lo, float hi) {
    u64 d;
    asm("mov.b64 %0, {%1, %2};" : "=l"(d) : "f"(lo), "f"(hi));
    return d;
}
__device__ __forceinline__ float2 unpack2(u64 v) {
    float2 f;
    asm("mov.b64 {%0, %1}, %2;" : "=f"(f.x), "=f"(f.y) : "l"(v));
    return f;
}

// ---------------------------------------------------------------------------
// Scratch (device globals — no allocation allowed)
// ---------------------------------------------------------------------------
__device__ float g_xproj[8ull * T_ * B_ * U_];
__device__ float g_seq[(size_t)C_ * T_ * B_ * U_];

// per-cell grid barrier state (4 independent sync domains of 32 blocks)
__device__ unsigned g_bar_count[C_] = {0, 0, 0, 0};
__device__ unsigned g_bar_gen[C_]   = {0, 0, 0, 0};

// ---------------------------------------------------------------------------
// Phase 1: input projection GEMM (unchanged from round 7)
// ---------------------------------------------------------------------------
#define PBM 128
#define PBN 64
#define PBK 8

__global__ __launch_bounds__(256) void proj_kernel(
    const float* __restrict__ x,
    const float* __restrict__ Wjx, const float* __restrict__ bjx,
    const float* __restrict__ Wkx, const float* __restrict__ bkx)
{
    __shared__ float As[PBK][PBM];
    __shared__ float Bs[PBK][PBN];

    const int zi = blockIdx.z;
    const int c  = zi >> 1;
    const int g  = zi & 1;
    const float* W  = (g ? Wkx : Wjx) + (size_t)c * D_ * U_;
    const float* bi = (g ? bkx : bjx) + (size_t)c * U_;

    const int m0 = blockIdx.x * PBM;
    const int n0 = blockIdx.y * PBN;
    const int tid = threadIdx.x;
    const int tx = tid & 15;
    const int ty = tid >> 4;

    u64 acc2[4][4];
#pragma unroll
    for (int i = 0; i < 4; i++)
#pragma unroll
        for (int j = 0; j < 4; j++) acc2[i][j] = 0ull;

    const int arow = tid >> 1;
    const int ak   = (tid & 1) << 2;
    const int brow = tid >> 4;
    const int bcol = (tid & 15) << 2;

    for (int k0 = 0; k0 < D_; k0 += PBK) {
        float4 av = *(const float4*)&x[(size_t)(m0 + arow) * D_ + k0 + ak];
        float4 bv = make_float4(0.f, 0.f, 0.f, 0.f);
        if (tid < 128)
            bv = *(const float4*)&W[(size_t)(k0 + brow) * U_ + n0 + bcol];
        __syncthreads();
        As[ak + 0][arow] = av.x;
        As[ak + 1][arow] = av.y;
        As[ak + 2][arow] = av.z;
        As[ak + 3][arow] = av.w;
        if (tid < 128)
            *(float4*)&Bs[brow][bcol] = bv;
        __syncthreads();
#pragma unroll
        for (int kk = 0; kk < PBK; kk++) {
            ulonglong2 aA = *(const ulonglong2*)&As[kk][ty << 3];
            ulonglong2 aB = *(const ulonglong2*)&As[kk][(ty << 3) + 4];
            float4 b4 = *(float4*)&Bs[kk][tx << 2];
            u64 bb0 = pack2(b4.x, b4.x);
            u64 bb1 = pack2(b4.y, b4.y);
            u64 bb2 = pack2(b4.z, b4.z);
            u64 bb3 = pack2(b4.w, b4.w);

            acc2[0][0] = ffma2(aA.x, bb0, acc2[0][0]);
            acc2[0][1] = ffma2(aA.x, bb1, acc2[0][1]);
            acc2[0][2] = ffma2(aA.x, bb2, acc2[0][2]);
            acc2[0][3] = ffma2(aA.x, bb3, acc2[0][3]);

            acc2[1][0] = ffma2(aA.y, bb0, acc2[1][0]);
            acc2[1][1] = ffma2(aA.y, bb1, acc2[1][1]);
            acc2[1][2] = ffma2(aA.y, bb2, acc2[1][2]);
            acc2[1][3] = ffma2(aA.y, bb3, acc2[1][3]);

            acc2[2][0] = ffma2(aB.x, bb0, acc2[2][0]);
            acc2[2][1] = ffma2(aB.x, bb1, acc2[2][1]);
            acc2[2][2] = ffma2(aB.x, bb2, acc2[2][2]);
            acc2[2][3] = ffma2(aB.x, bb3, acc2[2][3]);

            acc2[3][0] = ffma2(aB.y, bb0, acc2[3][0]);
            acc2[3][1] = ffma2(aB.y, bb1, acc2[3][1]);
            acc2[3][2] = ffma2(aB.y, bb2, acc2[3][2]);
            acc2[3][3] = ffma2(aB.y, bb3, acc2[3][3]);
        }
    }

    float accf[8][4];
#pragma unroll
    for (int ip = 0; ip < 4; ip++)
#pragma unroll
        for (int j = 0; j < 4; j++) {
            float2 p = unpack2(acc2[ip][j]);
            accf[2 * ip + 0][j] = p.x;
            accf[2 * ip + 1][j] = p.y;
        }

    float4 bias4 = *(const float4*)&bi[n0 + (tx << 2)];
#pragma unroll
    for (int i = 0; i < 8; i++) {
        int m  = m0 + (ty << 3) + i;
        int bb = m >> 9;
        int tt = m & 511;
        float4 o;
        o.x = accf[i][0] + bias4.x;
        o.y = accf[i][1] + bias4.y;
        o.z = accf[i][2] + bias4.z;
        o.w = accf[i][3] + bias4.w;
        size_t off = ((size_t)((zi * T_) + tt) * B_ + bb) * U_ + n0 + (tx << 2);
        *(float4*)&g_xproj[off] = o;
    }
}

// ---------------------------------------------------------------------------
// Phase 2: persistent flip-flop scan, 4-outputs-per-lane layout.
//   Block = (cell c, u-chunk of 16). 8 warps, warp w owns k in [w*64, w*64+64).
//   Lane l: s = l&3 -> k sub-slice [s*16, s*16+16); grp = l>>2 -> slots
//   {grp*4+j}, j=0..3 (slot = gate*16 + uu). Per batch: 4 LDS.128 -> 32 FFMA2.
//   Butterfly over the 4 sub-slices lands slot l's full 64-k sum on lane l.
// ---------------------------------------------------------------------------
#define SC_UC   16
#define SC_NCH  (U_ / SC_UC)             // 32 blocks per cell
#define SC_NBLK (C_ * SC_NCH)            // 128 blocks
#define SC_NTH  256
#define SC_NW   8

// per-warp h staging: 4 sub-slices, each [64 b][16 k], slice stride padded
#define HW_SLICE_STRIDE (B_ * 16 + 8)    // 1032 floats (bank offset 8)
#define HW_WARP_STRIDE  (4 * HW_SLICE_STRIDE)   // 4128 floats
#define HW_FLOATS       (SC_NW * HW_WARP_STRIDE)  // 33024
#define PART_FLOATS     (SC_NW * B_ * 32)         // 16384
#define SC_SMEM_FLOATS  (HW_FLOATS + PART_FLOATS + 32)
#define SC_SMEM_BYTES   (SC_SMEM_FLOATS * 4)      // 197,760 B

__device__ __forceinline__ void grid_barrier_cell(int c, unsigned nblocks)
{
    __threadfence();
    __syncthreads();
    if (threadIdx.x == 0) {
        unsigned gen0 = *(volatile unsigned*)&g_bar_gen[c];
        unsigned arr  = atomicAdd(&g_bar_count[c], 1u);
        if (arr == nblocks - 1) {
            g_bar_count[c] = 0;
            __threadfence();
            atomicAdd(&g_bar_gen[c], 1u);
        } else {
            while (*(volatile unsigned*)&g_bar_gen[c] == gen0) {
                __nanosleep(32);
            }
        }
        __threadfence();
    }
    __syncthreads();
}

// 4-way butterfly reduce over sub-slices; lane with sub-slice s keeps column s.
__device__ __forceinline__ float reduce4(float m0, float m1, float m2, float m3,
                                         int s)
{
    float q0 = __shfl_xor_sync(0xFFFFFFFFu, m0, 2);
    float q1 = __shfl_xor_sync(0xFFFFFFFFu, m1, 2);
    float q2 = __shfl_xor_sync(0xFFFFFFFFu, m2, 2);
    float q3 = __shfl_xor_sync(0xFFFFFFFFu, m3, 2);
    bool b1 = (s & 2) != 0;
    float n0 = b1 ? (m2 + q2) : (m0 + q0);
    float n1 = b1 ? (m3 + q3) : (m1 + q1);
    float r0 = __shfl_xor_sync(0xFFFFFFFFu, n0, 1);
    float r1 = __shfl_xor_sync(0xFFFFFFFFu, n1, 1);
    return (s & 1) ? (n1 + r1) : (n0 + r0);
}

__global__ __launch_bounds__(SC_NTH, 1) void scan_kernel(
    const float* __restrict__ h0,
    const float* __restrict__ Wjh, const float* __restrict__ bjh,
    const float* __restrict__ Wkh, const float* __restrict__ bkh)
{
    extern __shared__ float sm[];
    float* hw     = sm;                       // [NW][4][B_][16] padded
    float* part   = sm + HW_FLOATS;           // [NW][B_][32]
    float* bias_s = part + PART_FLOATS;       // [2][16]

    const int blk = blockIdx.x;
    const int c   = blk / SC_NCH;
    const int ch  = blk % SC_NCH;
    const int u0  = ch * SC_UC;
    const int tid = threadIdx.x;
    const int w   = tid >> 5;
    const int l   = tid & 31;
    const int s   = l & 3;                    // k sub-slice
    const int grp = l >> 2;                   // slot group

    // Weights: lane handles slots {grp*4+j}, k = w*64 + s*16 + [0,16),
    // packed in f32x2 pairs along k. 32 pairs = 64 regs.
    u64 wreg[4][8];
#pragma unroll
    for (int j = 0; j < 4; j++) {
        int sl = grp * 4 + j;                 // slot id 0..31
        int gate = sl >> 4;
        int uu = sl & 15;
        const float* Wsrc = (gate ? Wkh : Wjh) + (size_t)c * U_ * U_;
#pragma unroll
        for (int p = 0; p < 8; p++) {
            int k = w * 64 + s * 16 + 2 * p;
            wreg[j][p] = pack2(Wsrc[(size_t)k * U_ + u0 + uu],
                               Wsrc[(size_t)(k + 1) * U_ + u0 + uu]);
        }
    }

    if (tid < 32)
        bias_s[tid] = ((tid >> 4) ? bkh : bjh)[c * U_ + u0 + (tid & 15)];
    __syncthreads();

    float* hw_w  = hw + w * HW_WARP_STRIDE;
    const float* hw_me = hw_w + s * HW_SLICE_STRIDE;

    for (int t = 0; t < T_; t++) {
        // ---- per-warp staging: warp w loads its own 64-k slice of h ----
        const float* hsrc = (t == 0)
            ? (h0 + (size_t)c * B_ * U_)
            : (g_seq + ((size_t)(c * T_ + (t - 1)) * B_ * U_));
#pragma unroll 8
        for (int i = 0; i < 32; i++) {
            int chunk = l + i * 32;           // 0..1023
            int b  = chunk >> 4;
            int f4 = chunk & 15;
            int ss = f4 >> 2;
            int ip = f4 & 3;
            float4 v = __ldcg((const float4*)&hsrc[(size_t)b * U_ + w * 64 + f4 * 4]);
            *(float4*)&hw_w[ss * HW_SLICE_STRIDE + b * 16 + ip * 4] = v;
        }
        __syncwarp();

        // ---- matvec: 2 batches per iteration ----
        for (int b = 0; b < B_; b += 2) {
            const ulonglong2* q0 = (const ulonglong2*)&hw_me[(b + 0) * 16];
            const ulonglong2* q1 = (const ulonglong2*)&hw_me[(b + 1) * 16];
            ulonglong2 a0 = q0[0], a1 = q0[1], a2 = q0[2], a3 = q0[3];
            ulonglong2 c0 = q1[0], c1 = q1[1], c2 = q1[2], c3 = q1[3];
            u64 hA[8] = {a0.x, a0.y, a1.x, a1.y, a2.x, a2.y, a3.x, a3.y};
            u64 hB[8] = {c0.x, c0.y, c1.x, c1.y, c2.x, c2.y, c3.x, c3.y};
            u64 acc0[4] = {0ull, 0ull, 0ull, 0ull};
            u64 acc1[4] = {0ull, 0ull, 0ull, 0ull};
#pragma unroll
            for (int p = 0; p < 8; p++) {
#pragma unroll
                for (int j = 0; j < 4; j++) {
                    acc0[j] = ffma2(hA[p], wreg[j][p], acc0[j]);
                    acc1[j] = ffma2(hB[p], wreg[j][p], acc1[j]);
                }
            }
            float2 f;
            f = unpack2(acc0[0]); float m00 = f.x + f.y;
            f = unpack2(acc0[1]); float m01 = f.x + f.y;
            f = unpack2(acc0[2]); float m02 = f.x + f.y;
            f = unpack2(acc0[3]); float m03 = f.x + f.y;
            f = unpack2(acc1[0]); float m10 = f.x + f.y;
            f = unpack2(acc1[1]); float m11 = f.x + f.y;
            f = unpack2(acc1[2]); float m12 = f.x + f.y;
            f = unpack2(acc1[3]); float m13 = f.x + f.y;
            part[(w * B_ + b + 0) * 32 + l] = reduce4(m00, m01, m02, m03, s);
            part[(w * B_ + b + 1) * 32 + l] = reduce4(m10, m11, m12, m13, s);
        }
        __syncthreads();

        // ---- combine: reduce over warps, gates, flip-flop update, write ----
        float* seqout = g_seq + ((size_t)(c * T_ + t) * B_ * U_);
        const float* xj = g_xproj + ((size_t)((c * 2 + 0) * T_ + t) * B_ * U_);
        const float* xk = g_xproj + ((size_t)((c * 2 + 1) * T_ + t) * B_ * U_);
        const int wu = u0 >> 6;               // warp whose slice holds our u's
        const int su = (u0 >> 4) & 3;         // sub-slice within it
        const float* hold = hw + wu * HW_WARP_STRIDE + su * HW_SLICE_STRIDE;
#pragma unroll
        for (int r = 0; r < 4; r++) {
            int p  = tid + r * SC_NTH;        // 0..1023 = (b, u) pairs
            int pu = p & 15;
            int pb = p >> 4;
            float sj = 0.f, sk = 0.f;
#pragma unroll
            for (int ww = 0; ww < SC_NW; ww++) {
                sj += part[(ww * B_ + pb) * 32 + pu];
                sk += part[(ww * B_ + pb) * 32 + pu + 16];
            }
            float zj = sj + xj[pb * U_ + u0 + pu] + bias_s[pu];
            float zk = sk + xk[pb * U_ + u0 + pu] + bias_s[16 + pu];
            float jg = __fdividef(1.f, 1.f + __expf(-zj));
            float kg = __fdividef(1.f, 1.f + __expf(-zk));
            float h  = hold[pb * 16 + pu];
            float hn = jg * (1.f - h) + (1.f - kg) * h;
            seqout[pb * U_ + u0 + pu] = hn;
        }

        grid_barrier_cell(c, SC_NCH);
    }
}

// ---------------------------------------------------------------------------
// Phase 3: oscillator unroll (unchanged)
// ---------------------------------------------------------------------------
__global__ __launch_bounds__(256) void osc_kernel(float* __restrict__ out)
{
    int n = blockIdx.x * 256 + threadIdx.x;
    int u  = n & (U_ - 1);
    int bt = n >> 9;
    int b  = bt & (B_ - 1);
    int t  = bt >> 6;

    size_t base = (size_t)t * B_ * U_ + (size_t)b * U_ + u;
    const size_t plane = (size_t)T_ * B_ * U_;
    float phi = g_seq[0 * plane + base];
    float om  = g_seq[1 * plane + base];
    float r   = g_seq[2 * plane + base];
    float mu  = g_seq[3 * plane + base];

    float* o = out + ((size_t)b * (T_ * OSC_) + (size_t)t * OSC_) * U_ + u;
    o[0] = r * __cosf(phi);
#pragma unroll
    for (int sstep = 1; sstep < OSC_; sstep++) {
        r   = r + (mu - r * r) * r;
        phi = phi + om;
        o[(size_t)sstep * U_] = r * __cosf(phi);
    }
}

// ---------------------------------------------------------------------------
// Launch
// ---------------------------------------------------------------------------
extern "C" void kernel_launch(void* const* d_in, const int* in_sizes, int n_in,
                              void* d_out, int out_size)
{
    const float* x   = (const float*)d_in[0];
    const float* h0  = (const float*)d_in[1];
    const float* Wjx = (const float*)d_in[2];
    const float* bjx = (const float*)d_in[3];
    const float* Wjh = (const float*)d_in[4];
    const float* bjh = (const float*)d_in[5];
    const float* Wkx = (const float*)d_in[6];
    const float* bkx = (const float*)d_in[7];
    const float* Wkh = (const float*)d_in[8];
    const float* bkh = (const float*)d_in[9];
    float* out = (float*)d_out;
    (void)in_sizes; (void)n_in; (void)out_size;

    cudaFuncSetAttribute(scan_kernel,
                         cudaFuncAttributeMaxDynamicSharedMemorySize,
                         SC_SMEM_BYTES);

    dim3 pg((B_ * T_) / PBM, U_ / PBN, 8);
    proj_kernel<<<pg, 256>>>(x, Wjx, bjx, Wkx, bkx);

    scan_kernel<<<SC_NBLK, SC_NTH, SC_SMEM_BYTES>>>(h0, Wjh, bjh, Wkh, bkh);

    osc_kernel<<<(B_ * T_ * U_) / 256, 256>>>(out);
}

// round 10
// speedup vs baseline: 1.0946x; 1.0216x over previous
#include <cuda_runtime.h>
#include <cuda_bf16.h>
#include <cstdint>
#include <cstddef>

// Problem constants
#define C_ 4
#define B_ 64
#define T_ 512
#define D_ 256
#define U_ 512
#define OSC_ 5

typedef unsigned int u32;

// ---------------------------------------------------------------------------
// Helpers
// ---------------------------------------------------------------------------
__device__ __forceinline__ u32 prmt(u32 a, u32 b, u32 s) {
    u32 d;
    asm("prmt.b32 %0, %1, %2, %3;" : "=r"(d) : "r"(a), "r"(b), "r"(s));
    return d;
}

// pack two bf16 (k, k+1) into a .b32 mma operand (low half = lower k)
__device__ __forceinline__ u32 pack_bf(__nv_bfloat16 a, __nv_bfloat16 b) {
    return ((u32)__bfloat16_as_ushort(b) << 16) | (u32)__bfloat16_as_ushort(a);
}

// split fp32 into bf16 hi + bf16 lo (residual)
__device__ __forceinline__ void split_bf(float v, __nv_bfloat16& hi, __nv_bfloat16& lo) {
    hi = __float2bfloat16(v);
    lo = __float2bfloat16(v - __bfloat162float(hi));
}

// m16n8k16 bf16 mma, fp32 accumulate in place
__device__ __forceinline__ void mma16816(float d[4], u32 a0, u32 a1, u32 a2, u32 a3,
                                         u32 b0, u32 b1) {
    asm("mma.sync.aligned.m16n8k16.row.col.f32.bf16.bf16.f32 "
        "{%0,%1,%2,%3}, {%4,%5,%6,%7}, {%8,%9}, {%0,%1,%2,%3};"
        : "+f"(d[0]), "+f"(d[1]), "+f"(d[2]), "+f"(d[3])
        : "r"(a0), "r"(a1), "r"(a2), "r"(a3), "r"(b0), "r"(b1));
}

// ---------------------------------------------------------------------------
// Scratch (device globals — no allocation allowed)
// ---------------------------------------------------------------------------
__device__ float g_xproj[8ull * T_ * B_ * U_];
__device__ float g_seq[(size_t)C_ * T_ * B_ * U_];
// double-buffered packed h: low16 = bf16 hi, high16 = bf16 lo
__device__ u32 g_hsplit[2ull * C_ * B_ * U_];

// per-cell grid barrier state
__device__ unsigned g_bar_count[C_] = {0, 0, 0, 0};
__device__ unsigned g_bar_gen[C_]   = {0, 0, 0, 0};

// ---------------------------------------------------------------------------
// Phase 1: input projection GEMM via bf16 hi/lo split mma.
//   xproj[(c*2+g)][t][b][u] = sum_d x[b][t][d] * W[c][d][u] + bias[c][u]
//   Block tile 128m x 64n, K-chunks of 32. Warps: wm = w&1 (64m), wn = w>>1 (16n).
// ---------------------------------------------------------------------------
#define PJ_XPAD 40   // smem row stride (elems) for x tiles (conflict-free A loads)
#define PJ_WPAD 40   // smem row stride for transposed W tiles

__global__ __launch_bounds__(256) void proj_mma_kernel(
    const float* __restrict__ x,
    const float* __restrict__ Wjx, const float* __restrict__ bjx,
    const float* __restrict__ Wkx, const float* __restrict__ bkx)
{
    __shared__ __nv_bfloat16 xs_hi[128 * PJ_XPAD];
    __shared__ __nv_bfloat16 xs_lo[128 * PJ_XPAD];
    __shared__ __nv_bfloat16 ws_hi[64 * PJ_WPAD];   // transposed: [n][k]
    __shared__ __nv_bfloat16 ws_lo[64 * PJ_WPAD];

    const int zi = blockIdx.z;          // 0..7 = c*2+gate
    const int c  = zi >> 1;
    const int gt = zi & 1;
    const float* W  = (gt ? Wkx : Wjx) + (size_t)c * D_ * U_;
    const float* bi = (gt ? bkx : bjx) + (size_t)c * U_;

    const int m0 = blockIdx.x * 128;
    const int n0 = blockIdx.y * 64;
    const int tid = threadIdx.x;
    const int w   = tid >> 5;
    const int l   = tid & 31;
    const int g   = l >> 2;
    const int tg  = l & 3;
    const int wm  = w & 1;              // 0..1 : 64-row m slab
    const int wn  = w >> 1;             // 0..3 : 16-col n slab

    // bias for this lane's two columns per n-tile
    float2 bias2[2];
#pragma unroll
    for (int ni = 0; ni < 2; ni++)
        bias2[ni] = *(const float2*)&bi[n0 + wn * 16 + ni * 8 + tg * 2];

    float D[4][2][4];
#pragma unroll
    for (int mi = 0; mi < 4; mi++)
#pragma unroll
        for (int ni = 0; ni < 2; ni++)
#pragma unroll
            for (int q = 0; q < 4; q++) D[mi][ni][q] = 0.f;

    const int xr   = tid >> 1;          // 0..127 : x row
    const int half = tid & 1;           // which 16-col half
    const int wkr  = tid >> 3;          // 0..31 : W k-row
    const int wnc  = (tid & 7) * 8;     // W col group

    for (int kc = 0; kc < 8; kc++) {
        __syncthreads();                // previous chunk's mma done with smem
        // ---- stage x chunk (fp32 -> hi/lo bf16) ----
        const float* xp = &x[(size_t)(m0 + xr) * D_ + kc * 32 + half * 16];
#pragma unroll
        for (int q = 0; q < 4; q++) {
            float4 v = *(const float4*)&xp[q * 4];
            __nv_bfloat16 h0, l0, h1, l1, h2, l2, h3, l3;
            split_bf(v.x, h0, l0); split_bf(v.y, h1, l1);
            split_bf(v.z, h2, l2); split_bf(v.w, h3, l3);
            int e = xr * PJ_XPAD + half * 16 + q * 4;
            *(u32*)&xs_hi[e]     = pack_bf(h0, h1);
            *(u32*)&xs_hi[e + 2] = pack_bf(h2, h3);
            *(u32*)&xs_lo[e]     = pack_bf(l0, l1);
            *(u32*)&xs_lo[e + 2] = pack_bf(l2, l3);
        }
        // ---- stage W chunk, transposed to [n][k], hi/lo ----
        const float* wp = &W[(size_t)(kc * 32 + wkr) * U_ + n0 + wnc];
        float4 w0 = *(const float4*)wp;
        float4 w1 = *(const float4*)(wp + 4);
        float wv[8] = {w0.x, w0.y, w0.z, w0.w, w1.x, w1.y, w1.z, w1.w};
#pragma unroll
        for (int j = 0; j < 8; j++) {
            __nv_bfloat16 hh, ll;
            split_bf(wv[j], hh, ll);
            ws_hi[(wnc + j) * PJ_WPAD + wkr] = hh;
            ws_lo[(wnc + j) * PJ_WPAD + wkr] = ll;
        }
        __syncthreads();

        // ---- B fragments ----
        u32 Bh[2][2][2], Bl[2][2][2];
#pragma unroll
        for (int ni = 0; ni < 2; ni++)
#pragma unroll
            for (int ki = 0; ki < 2; ki++) {
                int e = (wn * 16 + ni * 8 + g) * PJ_WPAD + ki * 16 + tg * 2;
                Bh[ni][ki][0] = *(const u32*)&ws_hi[e];
                Bh[ni][ki][1] = *(const u32*)&ws_hi[e + 8];
                Bl[ni][ki][0] = *(const u32*)&ws_lo[e];
                Bl[ni][ki][1] = *(const u32*)&ws_lo[e + 8];
            }

        // ---- mma ----
#pragma unroll
        for (int mi = 0; mi < 4; mi++)
#pragma unroll
            for (int ki = 0; ki < 2; ki++) {
                int rb = (wm * 64 + mi * 16 + g) * PJ_XPAD + ki * 16 + tg * 2;
                u32 ah0 = *(const u32*)&xs_hi[rb];
                u32 ah1 = *(const u32*)&xs_hi[rb + 8 * PJ_XPAD];
                u32 ah2 = *(const u32*)&xs_hi[rb + 8];
                u32 ah3 = *(const u32*)&xs_hi[rb + 8 * PJ_XPAD + 8];
                u32 al0 = *(const u32*)&xs_lo[rb];
                u32 al1 = *(const u32*)&xs_lo[rb + 8 * PJ_XPAD];
                u32 al2 = *(const u32*)&xs_lo[rb + 8];
                u32 al3 = *(const u32*)&xs_lo[rb + 8 * PJ_XPAD + 8];
#pragma unroll
                for (int ni = 0; ni < 2; ni++) {
                    mma16816(D[mi][ni], ah0, ah1, ah2, ah3, Bh[ni][ki][0], Bh[ni][ki][1]);
                    mma16816(D[mi][ni], ah0, ah1, ah2, ah3, Bl[ni][ki][0], Bl[ni][ki][1]);
                    mma16816(D[mi][ni], al0, al1, al2, al3, Bh[ni][ki][0], Bh[ni][ki][1]);
                }
            }
    }

    // ---- epilogue: bias + scatter store ----
#pragma unroll
    for (int mi = 0; mi < 4; mi++)
#pragma unroll
        for (int ni = 0; ni < 2; ni++) {
            int col = n0 + wn * 16 + ni * 8 + tg * 2;
#pragma unroll
            for (int h = 0; h < 2; h++) {
                int m  = m0 + wm * 64 + mi * 16 + g + h * 8;
                int bb = m >> 9;
                int tt = m & 511;
                size_t off = ((size_t)(zi * T_ + tt) * B_ + bb) * U_ + col;
                float2 o;
                o.x = D[mi][ni][2 * h + 0] + bias2[ni].x;
                o.y = D[mi][ni][2 * h + 1] + bias2[ni].y;
                *(float2*)&g_xproj[off] = o;
            }
        }
}

// ---------------------------------------------------------------------------
// Phase 2: persistent flip-flop scan via tensor-core mma (bf16 hi/lo split).
//   Block = (cell c, u-chunk of 16). 8 warps, warp w owns k in [w*64,(w+1)*64).
//   Weights resident as B-fragments: 4 n-tiles (2 gates x 2) x 4 k-tiles x
//   (hi,lo) x 2 regs = 64 u32/thread.
//   h carried between steps in g_hsplit (packed hi|lo u32, double buffered);
//   staged per-warp into padded smem bf16 planes; 192 HMMA per warp per step.
// ---------------------------------------------------------------------------
#define SC_UC   16
#define SC_NCH  (U_ / SC_UC)             // 32 blocks per cell
#define SC_NBLK (C_ * SC_NCH)            // 128 blocks
#define SC_NTH  256
#define SC_NW   8
#define SC_KPAD 72                       // plane row stride (elems) -> conflict-free
#define SC_PLANE (B_ * SC_KPAD)          // per-warp plane elems (4608)
#define PART_STRIDE 34
#define PART_FLOATS (SC_NW * B_ * PART_STRIDE)   // 17408
#define SC_SMEM_BYTES (2 * SC_NW * SC_PLANE * 2 + PART_FLOATS * 4 + 128)

__device__ __forceinline__ void grid_barrier_cell(int c, unsigned nblocks)
{
    __threadfence();
    __syncthreads();
    if (threadIdx.x == 0) {
        unsigned gen0 = *(volatile unsigned*)&g_bar_gen[c];
        unsigned arr  = atomicAdd(&g_bar_count[c], 1u);
        if (arr == nblocks - 1) {
            g_bar_count[c] = 0;
            __threadfence();
            atomicAdd(&g_bar_gen[c], 1u);
        } else {
            while (*(volatile unsigned*)&g_bar_gen[c] == gen0) {
                __nanosleep(32);
            }
        }
        __threadfence();
    }
    __syncthreads();
}

__global__ __launch_bounds__(SC_NTH, 1) void scan_kernel(
    const float* __restrict__ h0,
    const float* __restrict__ Wjh, const float* __restrict__ bjh,
    const float* __restrict__ Wkh, const float* __restrict__ bkh)
{
    extern __shared__ char sm_raw[];
    __nv_bfloat16* sh_hi = (__nv_bfloat16*)sm_raw;             // [NW][B_][KPAD]
    __nv_bfloat16* sh_lo = sh_hi + SC_NW * SC_PLANE;
    float* part   = (float*)(sh_lo + SC_NW * SC_PLANE);        // [NW*B_][34]
    float* bias_s = part + PART_FLOATS;                        // [2][16]

    const int blk = blockIdx.x;
    const int c   = blk / SC_NCH;
    const int ch  = blk % SC_NCH;
    const int u0  = ch * SC_UC;
    const int tid = threadIdx.x;
    const int w   = tid >> 5;
    const int l   = tid & 31;
    const int g   = l >> 2;
    const int tg  = l & 3;

    // ---- resident weight B-fragments (hi/lo), one-time load ----
    u32 Bh[4][4][2], Bl[4][4][2];
#pragma unroll
    for (int ni = 0; ni < 4; ni++) {
        int gate = ni >> 1;
        int ucol = u0 + (ni & 1) * 8 + g;
        const float* Wc = (gate ? Wkh : Wjh) + (size_t)c * U_ * U_;
#pragma unroll
        for (int ki = 0; ki < 4; ki++) {
            int k0 = w * 64 + ki * 16 + tg * 2;
            float w00 = Wc[(size_t)(k0 + 0) * U_ + ucol];
            float w01 = Wc[(size_t)(k0 + 1) * U_ + ucol];
            float w08 = Wc[(size_t)(k0 + 8) * U_ + ucol];
            float w09 = Wc[(size_t)(k0 + 9) * U_ + ucol];
            __nv_bfloat16 h00, l00, h01b, l01, h08, l08, h09, l09;
            split_bf(w00, h00, l00); split_bf(w01, h01b, l01);
            split_bf(w08, h08, l08); split_bf(w09, h09, l09);
            Bh[ni][ki][0] = pack_bf(h00, h01b);
            Bh[ni][ki][1] = pack_bf(h08, h09);
            Bl[ni][ki][0] = pack_bf(l00, l01);
            Bl[ni][ki][1] = pack_bf(l08, l09);
        }
    }

    if (tid < 32)
        bias_s[tid] = ((tid >> 4) ? bkh : bjh)[c * U_ + u0 + (tid & 15)];
    __syncthreads();

    __nv_bfloat16* myhi = sh_hi + w * SC_PLANE;
    __nv_bfloat16* mylo = sh_lo + w * SC_PLANE;

    for (int t = 0; t < T_; t++) {
        // ---- per-warp staging of this warp's 64-k slice of h (all 64 b) ----
        if (t == 0) {
            const float* hs = h0 + (size_t)c * B_ * U_;
#pragma unroll 4
            for (int i = 0; i < 32; i++) {
                int chunk = l + i * 32;       // 0..1023
                int b  = chunk >> 4;
                int kq = chunk & 15;          // 4-elem group
                float4 v = __ldcg((const float4*)&hs[(size_t)b * U_ + w * 64 + kq * 4]);
                __nv_bfloat16 a0, b0, a1, b1, a2, b2, a3, b3;
                split_bf(v.x, a0, b0); split_bf(v.y, a1, b1);
                split_bf(v.z, a2, b2); split_bf(v.w, a3, b3);
                int e = b * SC_KPAD + kq * 4;
                *(u32*)&myhi[e]     = pack_bf(a0, a1);
                *(u32*)&myhi[e + 2] = pack_bf(a2, a3);
                *(u32*)&mylo[e]     = pack_bf(b0, b1);
                *(u32*)&mylo[e + 2] = pack_bf(b2, b3);
            }
        } else {
            const uint4* hs = (const uint4*)(g_hsplit
                + ((size_t)((t - 1) & 1) * C_ + c) * B_ * U_);
#pragma unroll 4
            for (int i = 0; i < 32; i++) {
                int chunk = l + i * 32;
                int b  = chunk >> 4;
                int kq = chunk & 15;
                uint4 v = __ldcg(&hs[b * (U_ / 4) + w * 16 + kq]);
                int e = b * SC_KPAD + kq * 4;
                *(u32*)&myhi[e]     = prmt(v.x, v.y, 0x5410);
                *(u32*)&myhi[e + 2] = prmt(v.z, v.w, 0x5410);
                *(u32*)&mylo[e]     = prmt(v.x, v.y, 0x7632);
                *(u32*)&mylo[e + 2] = prmt(v.z, v.w, 0x7632);
            }
        }
        __syncwarp();

        // ---- mma: z-partial for this warp's k slice, all 64 b x 32 slots ----
        float D[4][4][4];
#pragma unroll
        for (int mi = 0; mi < 4; mi++)
#pragma unroll
            for (int ni = 0; ni < 4; ni++)
#pragma unroll
                for (int q = 0; q < 4; q++) D[mi][ni][q] = 0.f;

#pragma unroll
        for (int mi = 0; mi < 4; mi++)
#pragma unroll
            for (int ki = 0; ki < 4; ki++) {
                int rb = (mi * 16 + g) * SC_KPAD + ki * 16 + tg * 2;
                u32 ah0 = *(const u32*)&myhi[rb];
                u32 ah1 = *(const u32*)&myhi[rb + 8 * SC_KPAD];
                u32 ah2 = *(const u32*)&myhi[rb + 8];
                u32 ah3 = *(const u32*)&myhi[rb + 8 * SC_KPAD + 8];
                u32 al0 = *(const u32*)&mylo[rb];
                u32 al1 = *(const u32*)&mylo[rb + 8 * SC_KPAD];
                u32 al2 = *(const u32*)&mylo[rb + 8];
                u32 al3 = *(const u32*)&mylo[rb + 8 * SC_KPAD + 8];
#pragma unroll
                for (int ni = 0; ni < 4; ni++) {
                    mma16816(D[mi][ni], ah0, ah1, ah2, ah3, Bh[ni][ki][0], Bh[ni][ki][1]);
                    mma16816(D[mi][ni], ah0, ah1, ah2, ah3, Bl[ni][ki][0], Bl[ni][ki][1]);
                    mma16816(D[mi][ni], al0, al1, al2, al3, Bh[ni][ki][0], Bh[ni][ki][1]);
                }
            }

        // ---- dump partials ----
#pragma unroll
        for (int mi = 0; mi < 4; mi++)
#pragma unroll
            for (int ni = 0; ni < 4; ni++) {
                float* pp = &part[(w * B_ + mi * 16 + g) * PART_STRIDE + ni * 8 + tg * 2];
                float2 lo2 = {D[mi][ni][0], D[mi][ni][1]};
                float2 hi2 = {D[mi][ni][2], D[mi][ni][3]};
                *(float2*)pp = lo2;
                *(float2*)(pp + 8 * PART_STRIDE) = hi2;
            }
        __syncthreads();

        // ---- combine: reduce over warps, gates, flip-flop update, write ----
        float* seqout = g_seq + ((size_t)(c * T_ + t) * B_ * U_);
        u32* hout = g_hsplit + ((size_t)(t & 1) * C_ + c) * B_ * U_;
        const float* xj = g_xproj + ((size_t)((c * 2 + 0) * T_ + t) * B_ * U_);
        const float* xk = g_xproj + ((size_t)((c * 2 + 1) * T_ + t) * B_ * U_);
        const int wu = u0 >> 6;               // warp whose plane holds our u's
        const int cu = u0 & 63;               // column base within that plane
        const __nv_bfloat16* hhi = sh_hi + wu * SC_PLANE;
        const __nv_bfloat16* hlo = sh_lo + wu * SC_PLANE;
#pragma unroll
        for (int r = 0; r < 4; r++) {
            int p  = tid + r * SC_NTH;        // 0..1023 = (b, u) pairs
            int pu = p & 15;
            int pb = p >> 4;
            float sj = 0.f, sk = 0.f;
#pragma unroll
            for (int ww = 0; ww < SC_NW; ww++) {
                sj += part[(ww * B_ + pb) * PART_STRIDE + pu];
                sk += part[(ww * B_ + pb) * PART_STRIDE + pu + 16];
            }
            float zj = sj + xj[pb * U_ + u0 + pu] + bias_s[pu];
            float zk = sk + xk[pb * U_ + u0 + pu] + bias_s[16 + pu];
            float jg = __fdividef(1.f, 1.f + __expf(-zj));
            float kg = __fdividef(1.f, 1.f + __expf(-zk));
            float h  = __bfloat162float(hhi[pb * SC_KPAD + cu + pu])
                     + __bfloat162float(hlo[pb * SC_KPAD + cu + pu]);
            float hn = jg * (1.f - h) + (1.f - kg) * h;
            seqout[pb * U_ + u0 + pu] = hn;
            __nv_bfloat16 nh, nl;
            split_bf(hn, nh, nl);
            hout[pb * U_ + u0 + pu] =
                ((u32)__bfloat16_as_ushort(nl) << 16) | (u32)__bfloat16_as_ushort(nh);
        }

        grid_barrier_cell(c, SC_NCH);
    }
}

// ---------------------------------------------------------------------------
// Phase 3: oscillator unroll (unchanged)
// ---------------------------------------------------------------------------
__global__ __launch_bounds__(256) void osc_kernel(float* __restrict__ out)
{
    int n = blockIdx.x * 256 + threadIdx.x;
    int u  = n & (U_ - 1);
    int bt = n >> 9;
    int b  = bt & (B_ - 1);
    int t  = bt >> 6;

    size_t base = (size_t)t * B_ * U_ + (size_t)b * U_ + u;
    const size_t plane = (size_t)T_ * B_ * U_;
    float phi = g_seq[0 * plane + base];
    float om  = g_seq[1 * plane + base];
    float r   = g_seq[2 * plane + base];
    float mu  = g_seq[3 * plane + base];

    float* o = out + ((size_t)b * (T_ * OSC_) + (size_t)t * OSC_) * U_ + u;
    o[0] = r * __cosf(phi);
#pragma unroll
    for (int sstep = 1; sstep < OSC_; sstep++) {
        r   = r + (mu - r * r) * r;
        phi = phi + om;
        o[(size_t)sstep * U_] = r * __cosf(phi);
    }
}

// ---------------------------------------------------------------------------
// Launch
// ---------------------------------------------------------------------------
extern "C" void kernel_launch(void* const* d_in, const int* in_sizes, int n_in,
                              void* d_out, int out_size)
{
    const float* x   = (const float*)d_in[0];
    const float* h0  = (const float*)d_in[1];
    const float* Wjx = (const float*)d_in[2];
    const float* bjx = (const float*)d_in[3];
    const float* Wjh = (const float*)d_in[4];
    const float* bjh = (const float*)d_in[5];
    const float* Wkx = (const float*)d_in[6];
    const float* bkx = (const float*)d_in[7];
    const float* Wkh = (const float*)d_in[8];
    const float* bkh = (const float*)d_in[9];
    float* out = (float*)d_out;
    (void)in_sizes; (void)n_in; (void)out_size;

    cudaFuncSetAttribute(scan_kernel,
                         cudaFuncAttributeMaxDynamicSharedMemorySize,
                         SC_SMEM_BYTES);

    // Phase 1: projections. grid = (M/128, U/64, 8 planes)
    dim3 pg((B_ * T_) / 128, U_ / 64, 8);
    proj_mma_kernel<<<pg, 256>>>(x, Wjx, bjx, Wkx, bkx);

    // Phase 2: persistent scan (128 co-resident blocks, per-cell grid barrier)
    scan_kernel<<<SC_NBLK, SC_NTH, SC_SMEM_BYTES>>>(h0, Wjh, bjh, Wkh, bkh);

    // Phase 3: oscillator
    osc_kernel<<<(B_ * T_ * U_) / 256, 256>>>(out);
}

// round 11
// speedup vs baseline: 1.7491x; 1.5980x over previous
#include <cuda_runtime.h>
#include <cuda_bf16.h>
#include <cstdint>
#include <cstddef>

// Problem constants
#define C_ 4
#define B_ 64
#define T_ 512
#define D_ 256
#define U_ 512
#define OSC_ 5

typedef unsigned int u32;

// ---------------------------------------------------------------------------
// Helpers
// ---------------------------------------------------------------------------
__device__ __forceinline__ u32 prmt(u32 a, u32 b, u32 s) {
    u32 d;
    asm("prmt.b32 %0, %1, %2, %3;" : "=r"(d) : "r"(a), "r"(b), "r"(s));
    return d;
}

// pack two bf16 (k, k+1) into a .b32 mma operand (low half = lower k)
__device__ __forceinline__ u32 pack_bf(__nv_bfloat16 a, __nv_bfloat16 b) {
    return ((u32)__bfloat16_as_ushort(b) << 16) | (u32)__bfloat16_as_ushort(a);
}

// split fp32 into bf16 hi + bf16 lo (residual)
__device__ __forceinline__ void split_bf(float v, __nv_bfloat16& hi, __nv_bfloat16& lo) {
    hi = __float2bfloat16(v);
    lo = __float2bfloat16(v - __bfloat162float(hi));
}

// m16n8k16 bf16 mma, fp32 accumulate in place
__device__ __forceinline__ void mma16816(float d[4], u32 a0, u32 a1, u32 a2, u32 a3,
                                         u32 b0, u32 b1) {
    asm("mma.sync.aligned.m16n8k16.row.col.f32.bf16.bf16.f32 "
        "{%0,%1,%2,%3}, {%4,%5,%6,%7}, {%8,%9}, {%0,%1,%2,%3};"
        : "+f"(d[0]), "+f"(d[1]), "+f"(d[2]), "+f"(d[3])
        : "r"(a0), "r"(a1), "r"(a2), "r"(a3), "r"(b0), "r"(b1));
}

__device__ __forceinline__ void ld2cg(u32& r0, u32& r1, const u32* p) {
    asm volatile("ld.global.cg.v2.u32 {%0,%1}, [%2];"
                 : "=r"(r0), "=r"(r1) : "l"(p));
}

// ---------------------------------------------------------------------------
// Scratch (device globals — no allocation allowed)
// ---------------------------------------------------------------------------
__device__ float g_xproj[8ull * T_ * B_ * U_];
__device__ float g_seq[(size_t)C_ * T_ * B_ * U_];
// double-buffered packed h: low16 = bf16 hi, high16 = bf16 lo
__device__ u32 g_hsplit[2ull * C_ * B_ * U_];

// per-cell grid barrier state (count self-resets; gen monotonic)
__device__ unsigned g_bar_count[C_] = {0, 0, 0, 0};
__device__ unsigned g_bar_gen[C_]   = {0, 0, 0, 0};

// ---------------------------------------------------------------------------
// Phase 1: input projection GEMM via bf16 hi/lo split mma (verified R9 kernel)
// ---------------------------------------------------------------------------
#define PJ_XPAD 40
#define PJ_WPAD 40

__global__ __launch_bounds__(256) void proj_mma_kernel(
    const float* __restrict__ x,
    const float* __restrict__ Wjx, const float* __restrict__ bjx,
    const float* __restrict__ Wkx, const float* __restrict__ bkx)
{
    __shared__ __nv_bfloat16 xs_hi[128 * PJ_XPAD];
    __shared__ __nv_bfloat16 xs_lo[128 * PJ_XPAD];
    __shared__ __nv_bfloat16 ws_hi[64 * PJ_WPAD];   // transposed: [n][k]
    __shared__ __nv_bfloat16 ws_lo[64 * PJ_WPAD];

    const int zi = blockIdx.z;          // 0..7 = c*2+gate
    const int c  = zi >> 1;
    const int gt = zi & 1;
    const float* W  = (gt ? Wkx : Wjx) + (size_t)c * D_ * U_;
    const float* bi = (gt ? bkx : bjx) + (size_t)c * U_;

    const int m0 = blockIdx.x * 128;
    const int n0 = blockIdx.y * 64;
    const int tid = threadIdx.x;
    const int w   = tid >> 5;
    const int l   = tid & 31;
    const int g   = l >> 2;
    const int tg  = l & 3;
    const int wm  = w & 1;
    const int wn  = w >> 1;

    float2 bias2[2];
#pragma unroll
    for (int ni = 0; ni < 2; ni++)
        bias2[ni] = *(const float2*)&bi[n0 + wn * 16 + ni * 8 + tg * 2];

    float D[4][2][4];
#pragma unroll
    for (int mi = 0; mi < 4; mi++)
#pragma unroll
        for (int ni = 0; ni < 2; ni++)
#pragma unroll
            for (int q = 0; q < 4; q++) D[mi][ni][q] = 0.f;

    const int xr   = tid >> 1;
    const int half = tid & 1;
    const int wkr  = tid >> 3;
    const int wnc  = (tid & 7) * 8;

    for (int kc = 0; kc < 8; kc++) {
        __syncthreads();
        const float* xp = &x[(size_t)(m0 + xr) * D_ + kc * 32 + half * 16];
#pragma unroll
        for (int q = 0; q < 4; q++) {
            float4 v = *(const float4*)&xp[q * 4];
            __nv_bfloat16 h0, l0, h1, l1, h2, l2, h3, l3;
            split_bf(v.x, h0, l0); split_bf(v.y, h1, l1);
            split_bf(v.z, h2, l2); split_bf(v.w, h3, l3);
            int e = xr * PJ_XPAD + half * 16 + q * 4;
            *(u32*)&xs_hi[e]     = pack_bf(h0, h1);
            *(u32*)&xs_hi[e + 2] = pack_bf(h2, h3);
            *(u32*)&xs_lo[e]     = pack_bf(l0, l1);
            *(u32*)&xs_lo[e + 2] = pack_bf(l2, l3);
        }
        const float* wp = &W[(size_t)(kc * 32 + wkr) * U_ + n0 + wnc];
        float4 w0 = *(const float4*)wp;
        float4 w1 = *(const float4*)(wp + 4);
        float wv[8] = {w0.x, w0.y, w0.z, w0.w, w1.x, w1.y, w1.z, w1.w};
#pragma unroll
        for (int j = 0; j < 8; j++) {
            __nv_bfloat16 hh, ll;
            split_bf(wv[j], hh, ll);
            ws_hi[(wnc + j) * PJ_WPAD + wkr] = hh;
            ws_lo[(wnc + j) * PJ_WPAD + wkr] = ll;
        }
        __syncthreads();

        u32 Bh[2][2][2], Bl[2][2][2];
#pragma unroll
        for (int ni = 0; ni < 2; ni++)
#pragma unroll
            for (int ki = 0; ki < 2; ki++) {
                int e = (wn * 16 + ni * 8 + g) * PJ_WPAD + ki * 16 + tg * 2;
                Bh[ni][ki][0] = *(const u32*)&ws_hi[e];
                Bh[ni][ki][1] = *(const u32*)&ws_hi[e + 8];
                Bl[ni][ki][0] = *(const u32*)&ws_lo[e];
                Bl[ni][ki][1] = *(const u32*)&ws_lo[e + 8];
            }

#pragma unroll
        for (int mi = 0; mi < 4; mi++)
#pragma unroll
            for (int ki = 0; ki < 2; ki++) {
                int rb = (wm * 64 + mi * 16 + g) * PJ_XPAD + ki * 16 + tg * 2;
                u32 ah0 = *(const u32*)&xs_hi[rb];
                u32 ah1 = *(const u32*)&xs_hi[rb + 8 * PJ_XPAD];
                u32 ah2 = *(const u32*)&xs_hi[rb + 8];
                u32 ah3 = *(const u32*)&xs_hi[rb + 8 * PJ_XPAD + 8];
                u32 al0 = *(const u32*)&xs_lo[rb];
                u32 al1 = *(const u32*)&xs_lo[rb + 8 * PJ_XPAD];
                u32 al2 = *(const u32*)&xs_lo[rb + 8];
                u32 al3 = *(const u32*)&xs_lo[rb + 8 * PJ_XPAD + 8];
#pragma unroll
                for (int ni = 0; ni < 2; ni++) {
                    mma16816(D[mi][ni], ah0, ah1, ah2, ah3, Bh[ni][ki][0], Bh[ni][ki][1]);
                    mma16816(D[mi][ni], ah0, ah1, ah2, ah3, Bl[ni][ki][0], Bl[ni][ki][1]);
                    mma16816(D[mi][ni], al0, al1, al2, al3, Bh[ni][ki][0], Bh[ni][ki][1]);
                }
            }
    }

#pragma unroll
    for (int mi = 0; mi < 4; mi++)
#pragma unroll
        for (int ni = 0; ni < 2; ni++) {
            int col = n0 + wn * 16 + ni * 8 + tg * 2;
#pragma unroll
            for (int h = 0; h < 2; h++) {
                int m  = m0 + wm * 64 + mi * 16 + g + h * 8;
                int bb = m >> 9;
                int tt = m & 511;
                size_t off = ((size_t)(zi * T_ + tt) * B_ + bb) * U_ + col;
                float2 o;
                o.x = D[mi][ni][2 * h + 0] + bias2[ni].x;
                o.y = D[mi][ni][2 * h + 1] + bias2[ni].y;
                *(float2*)&g_xproj[off] = o;
            }
        }
}

// ---------------------------------------------------------------------------
// Phase 2: persistent scan — direct global->register A-fragments, register
// h_prev, prefetched x, release/acquire split barrier.
// ---------------------------------------------------------------------------
#define SC_UC   16
#define SC_NCH  (U_ / SC_UC)             // 32 blocks per cell
#define SC_NBLK (C_ * SC_NCH)            // 128 blocks
#define SC_NTH  256
#define SC_NW   8
#define PART_STRIDE 34
#define PART_FLOATS (SC_NW * B_ * PART_STRIDE)   // 17408
#define SC_SMEM_BYTES (PART_FLOATS * 4)          // 69632

// load raw packed-h u32 pairs for one m-tile (16 LDG.64 -> 32 u32)
__device__ __forceinline__ void ld_mi_raw(u32* r, const u32* hin_w, int mi,
                                          int g, int tg)
{
    const u32* ra = hin_w + (size_t)(mi * 16 + g) * U_;
    const u32* rb = ra + 8 * U_;
#pragma unroll
    for (int ki = 0; ki < 4; ki++) {
        int kb = ki * 16 + tg * 2;
        ld2cg(r[ki * 8 + 0], r[ki * 8 + 1], ra + kb);
        ld2cg(r[ki * 8 + 2], r[ki * 8 + 3], rb + kb);
        ld2cg(r[ki * 8 + 4], r[ki * 8 + 5], ra + kb + 8);
        ld2cg(r[ki * 8 + 6], r[ki * 8 + 7], rb + kb + 8);
    }
}

__device__ __forceinline__ void mma_mi(const u32* r,
                                       const u32 Bh[4][4][2],
                                       const u32 Bl[4][4][2],
                                       float D[4][4])
{
#pragma unroll
    for (int ki = 0; ki < 4; ki++) {
        u32 ah0 = prmt(r[ki * 8 + 0], r[ki * 8 + 1], 0x5410);
        u32 al0 = prmt(r[ki * 8 + 0], r[ki * 8 + 1], 0x7632);
        u32 ah1 = prmt(r[ki * 8 + 2], r[ki * 8 + 3], 0x5410);
        u32 al1 = prmt(r[ki * 8 + 2], r[ki * 8 + 3], 0x7632);
        u32 ah2 = prmt(r[ki * 8 + 4], r[ki * 8 + 5], 0x5410);
        u32 al2 = prmt(r[ki * 8 + 4], r[ki * 8 + 5], 0x7632);
        u32 ah3 = prmt(r[ki * 8 + 6], r[ki * 8 + 7], 0x5410);
        u32 al3 = prmt(r[ki * 8 + 6], r[ki * 8 + 7], 0x7632);
#pragma unroll
        for (int ni = 0; ni < 4; ni++) {
            mma16816(D[ni], ah0, ah1, ah2, ah3, Bh[ni][ki][0], Bh[ni][ki][1]);
            mma16816(D[ni], ah0, ah1, ah2, ah3, Bl[ni][ki][0], Bl[ni][ki][1]);
            mma16816(D[ni], al0, al1, al2, al3, Bh[ni][ki][0], Bh[ni][ki][1]);
        }
    }
}

__global__ __launch_bounds__(SC_NTH, 1) void scan_kernel(
    const float* __restrict__ h0,
    const float* __restrict__ Wjh, const float* __restrict__ bjh,
    const float* __restrict__ Wkh, const float* __restrict__ bkh)
{
    extern __shared__ float part[];          // [NW][B_][PART_STRIDE]

    const int blk = blockIdx.x;
    const int c   = blk / SC_NCH;
    const int ch  = blk % SC_NCH;
    const int u0  = ch * SC_UC;
    const int tid = threadIdx.x;
    const int w   = tid >> 5;
    const int l   = tid & 31;
    const int g   = l >> 2;
    const int tg  = l & 3;
    const int pu  = tid & 15;                // combine slot: u offset (const)
    const int pb0 = tid >> 4;                // combine slot: base batch

    // ---- resident weight B-fragments (hi/lo), one-time load ----
    u32 Bh[4][4][2], Bl[4][4][2];
#pragma unroll
    for (int ni = 0; ni < 4; ni++) {
        int gate = ni >> 1;
        int ucol = u0 + (ni & 1) * 8 + g;
        const float* Wc = (gate ? Wkh : Wjh) + (size_t)c * U_ * U_;
#pragma unroll
        for (int ki = 0; ki < 4; ki++) {
            int k0 = w * 64 + ki * 16 + tg * 2;
            float w00 = Wc[(size_t)(k0 + 0) * U_ + ucol];
            float w01 = Wc[(size_t)(k0 + 1) * U_ + ucol];
            float w08 = Wc[(size_t)(k0 + 8) * U_ + ucol];
            float w09 = Wc[(size_t)(k0 + 9) * U_ + ucol];
            __nv_bfloat16 h00, l00, h01b, l01, h08, l08, h09, l09;
            split_bf(w00, h00, l00); split_bf(w01, h01b, l01);
            split_bf(w08, h08, l08); split_bf(w09, h09, l09);
            Bh[ni][ki][0] = pack_bf(h00, h01b);
            Bh[ni][ki][1] = pack_bf(h08, h09);
            Bl[ni][ki][0] = pack_bf(l00, l01);
            Bl[ni][ki][1] = pack_bf(l08, l09);
        }
    }

    const float bj_r = bjh[c * U_ + u0 + pu];
    const float bk_r = bkh[c * U_ + u0 + pu];

    // ---- pack h0 slice into buffer 0; keep h_prev in registers ----
    float hprev[4];
    {
        u32* buf0 = g_hsplit + (size_t)c * B_ * U_;    // buf index 0
#pragma unroll
        for (int r = 0; r < 4; r++) {
            int pb = pb0 + r * 16;
            float hv = h0[(size_t)c * B_ * U_ + (size_t)pb * U_ + u0 + pu];
            hprev[r] = hv;
            __nv_bfloat16 nh, nl;
            split_bf(hv, nh, nl);
            buf0[(size_t)pb * U_ + u0 + pu] =
                ((u32)__bfloat16_as_ushort(nl) << 16) | (u32)__bfloat16_as_ushort(nh);
        }
    }

    // ---- prefetch x projections for t = 0 ----
    float xjr[4], xkr[4];
    {
        const float* xj = g_xproj + ((size_t)(c * 2 + 0) * T_) * B_ * U_ + u0 + pu;
        const float* xk = g_xproj + ((size_t)(c * 2 + 1) * T_) * B_ * U_ + u0 + pu;
#pragma unroll
        for (int r = 0; r < 4; r++) {
            xjr[r] = __ldcs(&xj[(size_t)(pb0 + r * 16) * U_]);
            xkr[r] = __ldcs(&xk[(size_t)(pb0 + r * 16) * U_]);
        }
    }

    // ---- pre-loop cell barrier (publish h0 pack) ----
    __threadfence();
    __syncthreads();
    if (tid == 0) {
        unsigned gen0, old;
        asm volatile("ld.acquire.gpu.u32 %0, [%1];"
                     : "=r"(gen0) : "l"(&g_bar_gen[c]) : "memory");
        asm volatile("atom.acq_rel.gpu.add.u32 %0, [%1], 1;"
                     : "=r"(old) : "l"(&g_bar_count[c]) : "memory");
        if (old == SC_NCH - 1) {
            *(volatile unsigned*)&g_bar_count[c] = 0;
            asm volatile("red.release.gpu.add.u32 [%0], 1;"
                         :: "l"(&g_bar_gen[c]) : "memory");
        } else {
            unsigned gg;
            do {
                __nanosleep(20);
                asm volatile("ld.acquire.gpu.u32 %0, [%1];"
                             : "=r"(gg) : "l"(&g_bar_gen[c]) : "memory");
            } while (gg == gen0);
        }
    }
    __syncthreads();

    u32 rawA[32], rawB[32];

    for (int t = 0; t < T_; t++) {
        const u32* hin_w = g_hsplit
            + ((size_t)(t & 1) * C_ + c) * B_ * U_ + (size_t)w * 64;

        // ---- mma phase: 4 m-tiles, 2-stage pipelined direct frag loads ----
        ld_mi_raw(rawA, hin_w, 0, g, tg);
#pragma unroll
        for (int mi = 0; mi < 4; mi++) {
            u32* cur = (mi & 1) ? rawB : rawA;
            u32* nxt = (mi & 1) ? rawA : rawB;
            if (mi < 3) ld_mi_raw(nxt, hin_w, mi + 1, g, tg);
            float D[4][4];
#pragma unroll
            for (int ni = 0; ni < 4; ni++)
#pragma unroll
                for (int q = 0; q < 4; q++) D[ni][q] = 0.f;
            mma_mi(cur, Bh, Bl, D);
#pragma unroll
            for (int ni = 0; ni < 4; ni++) {
                float* pp = &part[(w * B_ + mi * 16 + g) * PART_STRIDE + ni * 8 + tg * 2];
                float2 lo2 = {D[ni][0], D[ni][1]};
                float2 hi2 = {D[ni][2], D[ni][3]};
                *(float2*)pp = lo2;
                *(float2*)(pp + 8 * PART_STRIDE) = hi2;
            }
        }
        __syncthreads();

        // ---- combine: reduce partials, gates, flip-flop update, write ----
        float* seqout = g_seq + ((size_t)(c * T_ + t)) * B_ * U_ + u0 + pu;
        u32* hout = g_hsplit
            + ((size_t)((t + 1) & 1) * C_ + c) * B_ * U_ + u0 + pu;
#pragma unroll
        for (int r = 0; r < 4; r++) {
            int pb = pb0 + r * 16;
            float sj = 0.f, sk = 0.f;
#pragma unroll
            for (int ww = 0; ww < SC_NW; ww++) {
                const float* pr = &part[(ww * B_ + pb) * PART_STRIDE];
                sj += pr[pu];
                sk += pr[pu + 16];
            }
            float zj = sj + xjr[r] + bj_r;
            float zk = sk + xkr[r] + bk_r;
            float jg = __fdividef(1.f, 1.f + __expf(-zj));
            float kg = __fdividef(1.f, 1.f + __expf(-zk));
            float h  = hprev[r];
            float hn = jg * (1.f - h) + (1.f - kg) * h;
            hprev[r] = hn;
            seqout[(size_t)pb * U_] = hn;
            __nv_bfloat16 nh, nl;
            split_bf(hn, nh, nl);
            hout[(size_t)pb * U_] =
                ((u32)__bfloat16_as_ushort(nl) << 16) | (u32)__bfloat16_as_ushort(nh);
        }

        if (t == T_ - 1) break;               // no barrier after final step

        // ---- barrier arrive (release) ----
        __threadfence();
        __syncthreads();
        unsigned gen0 = 0;
        bool leader_done = false;
        if (tid == 0) {
            unsigned old;
            asm volatile("ld.acquire.gpu.u32 %0, [%1];"
                         : "=r"(gen0) : "l"(&g_bar_gen[c]) : "memory");
            asm volatile("atom.acq_rel.gpu.add.u32 %0, [%1], 1;"
                         : "=r"(old) : "l"(&g_bar_count[c]) : "memory");
            if (old == SC_NCH - 1) {
                *(volatile unsigned*)&g_bar_count[c] = 0;
                asm volatile("red.release.gpu.add.u32 [%0], 1;"
                             :: "l"(&g_bar_gen[c]) : "memory");
                leader_done = true;
            }
        }

        // ---- prefetch x for t+1 while waiting ----
        {
            const float* xj = g_xproj
                + ((size_t)((c * 2 + 0) * T_ + t + 1)) * B_ * U_ + u0 + pu;
            const float* xk = g_xproj
                + ((size_t)((c * 2 + 1) * T_ + t + 1)) * B_ * U_ + u0 + pu;
#pragma unroll
            for (int r = 0; r < 4; r++) {
                xjr[r] = __ldcs(&xj[(size_t)(pb0 + r * 16) * U_]);
                xkr[r] = __ldcs(&xk[(size_t)(pb0 + r * 16) * U_]);
            }
        }

        // ---- barrier wait (acquire) ----
        if (tid == 0 && !leader_done) {
            unsigned gg;
            do {
                __nanosleep(20);
                asm volatile("ld.acquire.gpu.u32 %0, [%1];"
                             : "=r"(gg) : "l"(&g_bar_gen[c]) : "memory");
            } while (gg == gen0);
        }
        __syncthreads();
    }
}

// ---------------------------------------------------------------------------
// Phase 3: oscillator unroll (unchanged)
// ---------------------------------------------------------------------------
__global__ __launch_bounds__(256) void osc_kernel(float* __restrict__ out)
{
    int n = blockIdx.x * 256 + threadIdx.x;
    int u  = n & (U_ - 1);
    int bt = n >> 9;
    int b  = bt & (B_ - 1);
    int t  = bt >> 6;

    size_t base = (size_t)t * B_ * U_ + (size_t)b * U_ + u;
    const size_t plane = (size_t)T_ * B_ * U_;
    float phi = g_seq[0 * plane + base];
    float om  = g_seq[1 * plane + base];
    float r   = g_seq[2 * plane + base];
    float mu  = g_seq[3 * plane + base];

    float* o = out + ((size_t)b * (T_ * OSC_) + (size_t)t * OSC_) * U_ + u;
    o[0] = r * __cosf(phi);
#pragma unroll
    for (int sstep = 1; sstep < OSC_; sstep++) {
        r   = r + (mu - r * r) * r;
        phi = phi + om;
        o[(size_t)sstep * U_] = r * __cosf(phi);
    }
}

// ---------------------------------------------------------------------------
// Launch
// ---------------------------------------------------------------------------
extern "C" void kernel_launch(void* const* d_in, const int* in_sizes, int n_in,
                              void* d_out, int out_size)
{
    const float* x   = (const float*)d_in[0];
    const float* h0  = (const float*)d_in[1];
    const float* Wjx = (const float*)d_in[2];
    const float* bjx = (const float*)d_in[3];
    const float* Wjh = (const float*)d_in[4];
    const float* bjh = (const float*)d_in[5];
    const float* Wkx = (const float*)d_in[6];
    const float* bkx = (const float*)d_in[7];
    const float* Wkh = (const float*)d_in[8];
    const float* bkh = (const float*)d_in[9];
    float* out = (float*)d_out;
    (void)in_sizes; (void)n_in; (void)out_size;

    cudaFuncSetAttribute(scan_kernel,
                         cudaFuncAttributeMaxDynamicSharedMemorySize,
                         SC_SMEM_BYTES);

    // Phase 1: projections. grid = (M/128, U/64, 8 planes)
    dim3 pg((B_ * T_) / 128, U_ / 64, 8);
    proj_mma_kernel<<<pg, 256>>>(x, Wjx, bjx, Wkx, bkx);

    // Phase 2: persistent scan (128 co-resident blocks, per-cell barrier)
    scan_kernel<<<SC_NBLK, SC_NTH, SC_SMEM_BYTES>>>(h0, Wjh, bjh, Wkh, bkh);

    // Phase 3: oscillator
    osc_kernel<<<(B_ * T_ * U_) / 256, 256>>>(out);
}

// round 12
// speedup vs baseline: 1.9654x; 1.1236x over previous
#include <cuda_runtime.h>
#include <cuda_bf16.h>
#include <cstdint>
#include <cstddef>

// Problem constants
#define C_ 4
#define B_ 64
#define T_ 512
#define D_ 256
#define U_ 512
#define OSC_ 5

typedef unsigned int u32;

// ---------------------------------------------------------------------------
// Helpers
// ---------------------------------------------------------------------------
__device__ __forceinline__ u32 prmt(u32 a, u32 b, u32 s) {
    u32 d;
    asm("prmt.b32 %0, %1, %2, %3;" : "=r"(d) : "r"(a), "r"(b), "r"(s));
    return d;
}

__device__ __forceinline__ u32 pack_bf(__nv_bfloat16 a, __nv_bfloat16 b) {
    return ((u32)__bfloat16_as_ushort(b) << 16) | (u32)__bfloat16_as_ushort(a);
}

__device__ __forceinline__ void split_bf(float v, __nv_bfloat16& hi, __nv_bfloat16& lo) {
    hi = __float2bfloat16(v);
    lo = __float2bfloat16(v - __bfloat162float(hi));
}

__device__ __forceinline__ void mma16816(float d[4], u32 a0, u32 a1, u32 a2, u32 a3,
                                         u32 b0, u32 b1) {
    asm("mma.sync.aligned.m16n8k16.row.col.f32.bf16.bf16.f32 "
        "{%0,%1,%2,%3}, {%4,%5,%6,%7}, {%8,%9}, {%0,%1,%2,%3};"
        : "+f"(d[0]), "+f"(d[1]), "+f"(d[2]), "+f"(d[3])
        : "r"(a0), "r"(a1), "r"(a2), "r"(a3), "r"(b0), "r"(b1));
}

__device__ __forceinline__ void ld2cg(u32& r0, u32& r1, const u32* p) {
    asm volatile("ld.global.cg.v2.u32 {%0,%1}, [%2];"
                 : "=r"(r0), "=r"(r1) : "l"(p));
}

// ---------------------------------------------------------------------------
// Scratch (device globals — no allocation allowed)
// ---------------------------------------------------------------------------
__device__ float g_xproj[8ull * T_ * B_ * U_];
__device__ float g_seq[(size_t)C_ * T_ * B_ * U_];
// double-buffered packed h: low16 = bf16 hi, high16 = bf16 lo
__device__ u32 g_hsplit[2ull * C_ * B_ * U_];

// per-(cell,bgroup) barrier state: 8 domains of 16 blocks
__device__ unsigned g_bar_count[8] = {0};
__device__ unsigned g_bar_gen[8]   = {0};

// ---------------------------------------------------------------------------
// Phase 1: input projection GEMM via bf16 hi/lo split mma (verified R9-R11)
// ---------------------------------------------------------------------------
#define PJ_XPAD 40
#define PJ_WPAD 40

__global__ __launch_bounds__(256) void proj_mma_kernel(
    const float* __restrict__ x,
    const float* __restrict__ Wjx, const float* __restrict__ bjx,
    const float* __restrict__ Wkx, const float* __restrict__ bkx)
{
    __shared__ __nv_bfloat16 xs_hi[128 * PJ_XPAD];
    __shared__ __nv_bfloat16 xs_lo[128 * PJ_XPAD];
    __shared__ __nv_bfloat16 ws_hi[64 * PJ_WPAD];
    __shared__ __nv_bfloat16 ws_lo[64 * PJ_WPAD];

    const int zi = blockIdx.z;
    const int c  = zi >> 1;
    const int gt = zi & 1;
    const float* W  = (gt ? Wkx : Wjx) + (size_t)c * D_ * U_;
    const float* bi = (gt ? bkx : bjx) + (size_t)c * U_;

    const int m0 = blockIdx.x * 128;
    const int n0 = blockIdx.y * 64;
    const int tid = threadIdx.x;
    const int w   = tid >> 5;
    const int l   = tid & 31;
    const int g   = l >> 2;
    const int tg  = l & 3;
    const int wm  = w & 1;
    const int wn  = w >> 1;

    float2 bias2[2];
#pragma unroll
    for (int ni = 0; ni < 2; ni++)
        bias2[ni] = *(const float2*)&bi[n0 + wn * 16 + ni * 8 + tg * 2];

    float D[4][2][4];
#pragma unroll
    for (int mi = 0; mi < 4; mi++)
#pragma unroll
        for (int ni = 0; ni < 2; ni++)
#pragma unroll
            for (int q = 0; q < 4; q++) D[mi][ni][q] = 0.f;

    const int xr   = tid >> 1;
    const int half = tid & 1;
    const int wkr  = tid >> 3;
    const int wnc  = (tid & 7) * 8;

    for (int kc = 0; kc < 8; kc++) {
        __syncthreads();
        const float* xp = &x[(size_t)(m0 + xr) * D_ + kc * 32 + half * 16];
#pragma unroll
        for (int q = 0; q < 4; q++) {
            float4 v = *(const float4*)&xp[q * 4];
            __nv_bfloat16 h0, l0, h1, l1, h2, l2, h3, l3;
            split_bf(v.x, h0, l0); split_bf(v.y, h1, l1);
            split_bf(v.z, h2, l2); split_bf(v.w, h3, l3);
            int e = xr * PJ_XPAD + half * 16 + q * 4;
            *(u32*)&xs_hi[e]     = pack_bf(h0, h1);
            *(u32*)&xs_hi[e + 2] = pack_bf(h2, h3);
            *(u32*)&xs_lo[e]     = pack_bf(l0, l1);
            *(u32*)&xs_lo[e + 2] = pack_bf(l2, l3);
        }
        const float* wp = &W[(size_t)(kc * 32 + wkr) * U_ + n0 + wnc];
        float4 w0 = *(const float4*)wp;
        float4 w1 = *(const float4*)(wp + 4);
        float wv[8] = {w0.x, w0.y, w0.z, w0.w, w1.x, w1.y, w1.z, w1.w};
#pragma unroll
        for (int j = 0; j < 8; j++) {
            __nv_bfloat16 hh, ll;
            split_bf(wv[j], hh, ll);
            ws_hi[(wnc + j) * PJ_WPAD + wkr] = hh;
            ws_lo[(wnc + j) * PJ_WPAD + wkr] = ll;
        }
        __syncthreads();

        u32 Bh[2][2][2], Bl[2][2][2];
#pragma unroll
        for (int ni = 0; ni < 2; ni++)
#pragma unroll
            for (int ki = 0; ki < 2; ki++) {
                int e = (wn * 16 + ni * 8 + g) * PJ_WPAD + ki * 16 + tg * 2;
                Bh[ni][ki][0] = *(const u32*)&ws_hi[e];
                Bh[ni][ki][1] = *(const u32*)&ws_hi[e + 8];
                Bl[ni][ki][0] = *(const u32*)&ws_lo[e];
                Bl[ni][ki][1] = *(const u32*)&ws_lo[e + 8];
            }

#pragma unroll
        for (int mi = 0; mi < 4; mi++)
#pragma unroll
            for (int ki = 0; ki < 2; ki++) {
                int rb = (wm * 64 + mi * 16 + g) * PJ_XPAD + ki * 16 + tg * 2;
                u32 ah0 = *(const u32*)&xs_hi[rb];
                u32 ah1 = *(const u32*)&xs_hi[rb + 8 * PJ_XPAD];
                u32 ah2 = *(const u32*)&xs_hi[rb + 8];
                u32 ah3 = *(const u32*)&xs_hi[rb + 8 * PJ_XPAD + 8];
                u32 al0 = *(const u32*)&xs_lo[rb];
                u32 al1 = *(const u32*)&xs_lo[rb + 8 * PJ_XPAD];
                u32 al2 = *(const u32*)&xs_lo[rb + 8];
                u32 al3 = *(const u32*)&xs_lo[rb + 8 * PJ_XPAD + 8];
#pragma unroll
                for (int ni = 0; ni < 2; ni++) {
                    mma16816(D[mi][ni], ah0, ah1, ah2, ah3, Bh[ni][ki][0], Bh[ni][ki][1]);
                    mma16816(D[mi][ni], ah0, ah1, ah2, ah3, Bl[ni][ki][0], Bl[ni][ki][1]);
                    mma16816(D[mi][ni], al0, al1, al2, al3, Bh[ni][ki][0], Bh[ni][ki][1]);
                }
            }
    }

#pragma unroll
    for (int mi = 0; mi < 4; mi++)
#pragma unroll
        for (int ni = 0; ni < 2; ni++) {
            int col = n0 + wn * 16 + ni * 8 + tg * 2;
#pragma unroll
            for (int h = 0; h < 2; h++) {
                int m  = m0 + wm * 64 + mi * 16 + g + h * 8;
                int bb = m >> 9;
                int tt = m & 511;
                size_t off = ((size_t)(zi * T_ + tt) * B_ + bb) * U_ + col;
                float2 o;
                o.x = D[mi][ni][2 * h + 0] + bias2[ni].x;
                o.y = D[mi][ni][2 * h + 1] + bias2[ni].y;
                *(float2*)&g_xproj[off] = o;
            }
        }
}

// ---------------------------------------------------------------------------
// Phase 2: persistent scan — (cell, bgroup of 32 b, u-chunk of 32 u) CTAs.
//   128 CTAs, 1 per SM. Weights in smem (hi|lo packed uint2), h via L2,
//   16-block sync domains.
// ---------------------------------------------------------------------------
#define NBG  2
#define BPG  32                          // batches per group
#define NUC  16
#define UC   32                          // u per CTA (64 gate-cols)
#define KST  260                         // uint2 per col (256 + pad)
#define W_SMEM_U2 (64 * KST)             // 16640 uint2 = 133120 B
#define PSTRIDE 66
#define PART_FLOATS (8 * BPG * PSTRIDE)  // 16896 floats = 67584 B
#define SC_SMEM_BYTES (W_SMEM_U2 * 8 + PART_FLOATS * 4)   // 200704 B
#define SC_DOM_BLKS 16

// raw packed-h loads for one m-tile (16 ld.cg.v2 -> 32 u32)
__device__ __forceinline__ void ld_mi_raw(u32* r, const u32* hin_w, int mi,
                                          int g, int tg)
{
    const u32* ra = hin_w + (size_t)(mi * 16 + g) * U_;
    const u32* rb = ra + 8 * U_;
#pragma unroll
    for (int ki = 0; ki < 4; ki++) {
        int kb = ki * 16 + tg * 2;
        ld2cg(r[ki * 8 + 0], r[ki * 8 + 1], ra + kb);
        ld2cg(r[ki * 8 + 2], r[ki * 8 + 3], rb + kb);
        ld2cg(r[ki * 8 + 4], r[ki * 8 + 5], ra + kb + 8);
        ld2cg(r[ki * 8 + 6], r[ki * 8 + 7], rb + kb + 8);
    }
}

__global__ __launch_bounds__(256, 1) void scan_kernel(
    const float* __restrict__ h0,
    const float* __restrict__ Wjh, const float* __restrict__ bjh,
    const float* __restrict__ Wkh, const float* __restrict__ bkh)
{
    extern __shared__ char smraw[];
    uint2* ws   = (uint2*)smraw;                     // [64 cols][KST]
    float* part = (float*)(smraw + W_SMEM_U2 * 8);   // [8 w][BPG][PSTRIDE]

    const int blk = blockIdx.x;          // c*32 + bg*16 + nc
    const int c   = blk >> 5;
    const int bg  = (blk >> 4) & 1;
    const int nc  = blk & 15;
    const int dom = c * 2 + bg;
    const int tid = threadIdx.x;
    const int w   = tid >> 5;
    const int l   = tid & 31;
    const int g   = l >> 2;
    const int tg  = l & 3;
    const int pu  = tid & 31;            // combine: u offset
    const int pbq = tid >> 5;            // combine: base batch (0..7)

    // ---- one-time: weights -> smem (hi|lo packed pairs along k) ----
    for (int idx = tid; idx < 64 * 256; idx += 256) {
        int col  = idx >> 8;             // 0..63 = gate*32 + uu
        int kk   = idx & 255;
        int gate = col >> 5;
        int uu   = col & 31;
        const float* Wc = (gate ? Wkh : Wjh) + (size_t)c * U_ * U_;
        int ucol = nc * UC + uu;
        float w0 = Wc[(size_t)(2 * kk + 0) * U_ + ucol];
        float w1 = Wc[(size_t)(2 * kk + 1) * U_ + ucol];
        __nv_bfloat16 h0b, l0b, h1b, l1b;
        split_bf(w0, h0b, l0b);
        split_bf(w1, h1b, l1b);
        ws[col * KST + kk] = make_uint2(pack_bf(h0b, h1b), pack_bf(l0b, l1b));
    }

    const float bj_r = bjh[c * U_ + nc * UC + pu];
    const float bk_r = bkh[c * U_ + nc * UC + pu];

    // ---- pack h0 slice into buffer 0; h_prev in registers ----
    float hprev[4];
    {
        u32* buf0 = g_hsplit + (size_t)c * B_ * U_;
#pragma unroll
        for (int r = 0; r < 4; r++) {
            int b = bg * BPG + pbq + r * 8;
            float hv = h0[(size_t)c * B_ * U_ + (size_t)b * U_ + nc * UC + pu];
            hprev[r] = hv;
            __nv_bfloat16 nh, nl;
            split_bf(hv, nh, nl);
            buf0[(size_t)b * U_ + nc * UC + pu] =
                ((u32)__bfloat16_as_ushort(nl) << 16) | (u32)__bfloat16_as_ushort(nh);
        }
    }

    // ---- prefetch x projections for t = 0 ----
    float xjr[4], xkr[4];
    {
        const float* xj = g_xproj + ((size_t)(c * 2 + 0) * T_) * B_ * U_
                          + (size_t)(bg * BPG) * U_ + nc * UC + pu;
        const float* xk = g_xproj + ((size_t)(c * 2 + 1) * T_) * B_ * U_
                          + (size_t)(bg * BPG) * U_ + nc * UC + pu;
#pragma unroll
        for (int r = 0; r < 4; r++) {
            xjr[r] = __ldcs(&xj[(size_t)(pbq + r * 8) * U_]);
            xkr[r] = __ldcs(&xk[(size_t)(pbq + r * 8) * U_]);
        }
    }

    // ---- pre-loop domain barrier (publish h0 pack + smem weights) ----
    __threadfence();
    __syncthreads();
    if (tid == 0) {
        unsigned gen0, old;
        asm volatile("ld.acquire.gpu.u32 %0, [%1];"
                     : "=r"(gen0) : "l"(&g_bar_gen[dom]) : "memory");
        asm volatile("atom.acq_rel.gpu.add.u32 %0, [%1], 1;"
                     : "=r"(old) : "l"(&g_bar_count[dom]) : "memory");
        if (old == SC_DOM_BLKS - 1) {
            *(volatile unsigned*)&g_bar_count[dom] = 0;
            asm volatile("red.release.gpu.add.u32 [%0], 1;"
                         :: "l"(&g_bar_gen[dom]) : "memory");
        } else {
            unsigned gg;
            do {
                __nanosleep(20);
                asm volatile("ld.acquire.gpu.u32 %0, [%1];"
                             : "=r"(gg) : "l"(&g_bar_gen[dom]) : "memory");
            } while (gg == gen0);
        }
    }
    __syncthreads();

    u32 raw0[32], raw1[32];

    for (int t = 0; t < T_; t++) {
        const u32* hin_w = g_hsplit
            + ((size_t)(t & 1) * C_ + c) * B_ * U_
            + (size_t)(bg * BPG) * U_ + (size_t)w * 64;

        // ---- load both m-tiles' raw h (high MLP, L2) ----
        ld_mi_raw(raw0, hin_w, 0, g, tg);
        ld_mi_raw(raw1, hin_w, 1, g, tg);

        float D[2][8][4];
#pragma unroll
        for (int mt = 0; mt < 2; mt++)
#pragma unroll
            for (int ni = 0; ni < 8; ni++)
#pragma unroll
                for (int q = 0; q < 4; q++) D[mt][ni][q] = 0.f;

#pragma unroll
        for (int ki = 0; ki < 4; ki++) {
            const u32* r0 = raw0 + ki * 8;
            const u32* r1 = raw1 + ki * 8;
            u32 a0h = prmt(r0[0], r0[1], 0x5410), a0l = prmt(r0[0], r0[1], 0x7632);
            u32 a1h = prmt(r0[2], r0[3], 0x5410), a1l = prmt(r0[2], r0[3], 0x7632);
            u32 a2h = prmt(r0[4], r0[5], 0x5410), a2l = prmt(r0[4], r0[5], 0x7632);
            u32 a3h = prmt(r0[6], r0[7], 0x5410), a3l = prmt(r0[6], r0[7], 0x7632);
            u32 b0h = prmt(r1[0], r1[1], 0x5410), b0l = prmt(r1[0], r1[1], 0x7632);
            u32 b1h = prmt(r1[2], r1[3], 0x5410), b1l = prmt(r1[2], r1[3], 0x7632);
            u32 b2h = prmt(r1[4], r1[5], 0x5410), b2l = prmt(r1[4], r1[5], 0x7632);
            u32 b3h = prmt(r1[6], r1[7], 0x5410), b3l = prmt(r1[6], r1[7], 0x7632);
            int kkb = w * 32 + ki * 8 + tg;
#pragma unroll
            for (int ni = 0; ni < 8; ni++) {
                uint2 v0 = ws[(ni * 8 + g) * KST + kkb];
                uint2 v1 = ws[(ni * 8 + g) * KST + kkb + 4];
                mma16816(D[0][ni], a0h, a1h, a2h, a3h, v0.x, v1.x);
                mma16816(D[0][ni], a0h, a1h, a2h, a3h, v0.y, v1.y);
                mma16816(D[0][ni], a0l, a1l, a2l, a3l, v0.x, v1.x);
                mma16816(D[1][ni], b0h, b1h, b2h, b3h, v0.x, v1.x);
                mma16816(D[1][ni], b0h, b1h, b2h, b3h, v0.y, v1.y);
                mma16816(D[1][ni], b0l, b1l, b2l, b3l, v0.x, v1.x);
            }
        }

        // ---- store partials ----
#pragma unroll
        for (int mt = 0; mt < 2; mt++)
#pragma unroll
            for (int ni = 0; ni < 8; ni++) {
                float* pp = &part[(w * BPG + mt * 16 + g) * PSTRIDE + ni * 8 + tg * 2];
                float2 lo2 = {D[mt][ni][0], D[mt][ni][1]};
                float2 hi2 = {D[mt][ni][2], D[mt][ni][3]};
                *(float2*)pp = lo2;
                *(float2*)(pp + 8 * PSTRIDE) = hi2;
            }
        __syncthreads();

        // ---- combine: reduce over 8 k-warps, gates, flip-flop, write ----
        float* seqout = g_seq + ((size_t)(c * T_ + t)) * B_ * U_
                        + (size_t)(bg * BPG) * U_ + nc * UC + pu;
        u32* hout = g_hsplit + ((size_t)((t + 1) & 1) * C_ + c) * B_ * U_
                    + (size_t)(bg * BPG) * U_ + nc * UC + pu;
#pragma unroll
        for (int r = 0; r < 4; r++) {
            int pb = pbq + r * 8;
            float sj = 0.f, sk = 0.f;
#pragma unroll
            for (int ww = 0; ww < 8; ww++) {
                const float* pr = &part[(ww * BPG + pb) * PSTRIDE];
                sj += pr[pu];
                sk += pr[pu + 32];
            }
            float zj = sj + xjr[r] + bj_r;
            float zk = sk + xkr[r] + bk_r;
            float jg = __fdividef(1.f, 1.f + __expf(-zj));
            float kg = __fdividef(1.f, 1.f + __expf(-zk));
            float h  = hprev[r];
            float hn = jg * (1.f - h) + (1.f - kg) * h;
            hprev[r] = hn;
            seqout[(size_t)pb * U_] = hn;
            __nv_bfloat16 nh, nl;
            split_bf(hn, nh, nl);
            hout[(size_t)pb * U_] =
                ((u32)__bfloat16_as_ushort(nl) << 16) | (u32)__bfloat16_as_ushort(nh);
        }

        if (t == T_ - 1) break;

        // ---- barrier arrive (release) ----
        __threadfence();
        __syncthreads();
        unsigned gen0 = 0;
        bool leader_done = false;
        if (tid == 0) {
            unsigned old;
            asm volatile("ld.acquire.gpu.u32 %0, [%1];"
                         : "=r"(gen0) : "l"(&g_bar_gen[dom]) : "memory");
            asm volatile("atom.acq_rel.gpu.add.u32 %0, [%1], 1;"
                         : "=r"(old) : "l"(&g_bar_count[dom]) : "memory");
            if (old == SC_DOM_BLKS - 1) {
                *(volatile unsigned*)&g_bar_count[dom] = 0;
                asm volatile("red.release.gpu.add.u32 [%0], 1;"
                             :: "l"(&g_bar_gen[dom]) : "memory");
                leader_done = true;
            }
        }

        // ---- prefetch x for t+1 while waiting ----
        {
            const float* xj = g_xproj
                + ((size_t)((c * 2 + 0) * T_ + t + 1)) * B_ * U_
                + (size_t)(bg * BPG) * U_ + nc * UC + pu;
            const float* xk = g_xproj
                + ((size_t)((c * 2 + 1) * T_ + t + 1)) * B_ * U_
                + (size_t)(bg * BPG) * U_ + nc * UC + pu;
#pragma unroll
            for (int r = 0; r < 4; r++) {
                xjr[r] = __ldcs(&xj[(size_t)(pbq + r * 8) * U_]);
                xkr[r] = __ldcs(&xk[(size_t)(pbq + r * 8) * U_]);
            }
        }

        // ---- barrier wait (acquire) ----
        if (tid == 0 && !leader_done) {
            unsigned gg;
            do {
                __nanosleep(20);
                asm volatile("ld.acquire.gpu.u32 %0, [%1];"
                             : "=r"(gg) : "l"(&g_bar_gen[dom]) : "memory");
            } while (gg == gen0);
        }
        __syncthreads();
    }
}

// ---------------------------------------------------------------------------
// Phase 3: oscillator unroll (unchanged)
// ---------------------------------------------------------------------------
__global__ __launch_bounds__(256) void osc_kernel(float* __restrict__ out)
{
    int n = blockIdx.x * 256 + threadIdx.x;
    int u  = n & (U_ - 1);
    int bt = n >> 9;
    int b  = bt & (B_ - 1);
    int t  = bt >> 6;

    size_t base = (size_t)t * B_ * U_ + (size_t)b * U_ + u;
    const size_t plane = (size_t)T_ * B_ * U_;
    float phi = g_seq[0 * plane + base];
    float om  = g_seq[1 * plane + base];
    float r   = g_seq[2 * plane + base];
    float mu  = g_seq[3 * plane + base];

    float* o = out + ((size_t)b * (T_ * OSC_) + (size_t)t * OSC_) * U_ + u;
    o[0] = r * __cosf(phi);
#pragma unroll
    for (int sstep = 1; sstep < OSC_; sstep++) {
        r   = r + (mu - r * r) * r;
        phi = phi + om;
        o[(size_t)sstep * U_] = r * __cosf(phi);
    }
}

// ---------------------------------------------------------------------------
// Launch
// ---------------------------------------------------------------------------
extern "C" void kernel_launch(void* const* d_in, const int* in_sizes, int n_in,
                              void* d_out, int out_size)
{
    const float* x   = (const float*)d_in[0];
    const float* h0  = (const float*)d_in[1];
    const float* Wjx = (const float*)d_in[2];
    const float* bjx = (const float*)d_in[3];
    const float* Wjh = (const float*)d_in[4];
    const float* bjh = (const float*)d_in[5];
    const float* Wkx = (const float*)d_in[6];
    const float* bkx = (const float*)d_in[7];
    const float* Wkh = (const float*)d_in[8];
    const float* bkh = (const float*)d_in[9];
    float* out = (float*)d_out;
    (void)in_sizes; (void)n_in; (void)out_size;

    cudaFuncSetAttribute(scan_kernel,
                         cudaFuncAttributeMaxDynamicSharedMemorySize,
                         SC_SMEM_BYTES);

    // Phase 1: projections. grid = (M/128, U/64, 8 planes)
    dim3 pg((B_ * T_) / 128, U_ / 64, 8);
    proj_mma_kernel<<<pg, 256>>>(x, Wjx, bjx, Wkx, bkx);

    // Phase 2: persistent scan — 128 CTAs (4 cells x 2 bgroups x 16 u-chunks)
    scan_kernel<<<C_ * NBG * NUC, 256, SC_SMEM_BYTES>>>(h0, Wjh, bjh, Wkh, bkh);

    // Phase 3: oscillator
    osc_kernel<<<(B_ * T_ * U_) / 256, 256>>>(out);
}